// round 10
// baseline (speedup 1.0000x reference)
#include <cuda_runtime.h>
#include <cuda_bf16.h>
#include <cstdint>

#define BATCH 64
#define NPIX  196
#define C1    2048
#define C2    512
#define KCONV 18432
#define K4    4096
#define EPSF  1e-6f

typedef __nv_bfloat16 bf16;

// ---------------- scratch (device globals; no allocation) ----------------
__device__ float g_x [(size_t)BATCH * C2 * NPIX];   // conv+bn+relu output (fp32)
__device__ float g_x2[(size_t)BATCH * C2 * NPIX];   // GCEM output (fp32)
__device__ float g_zt[(size_t)BATCH * 8  * NPIX];   // attention maps (fp32)
__device__ float g_xb[(size_t)BATCH * C1 * NPIX];   // conv4(concat) output (fp32)
__device__ float g_xd[(size_t)BATCH * 32 * NPIX];   // downconv (fp32)
__device__ float g_xc[(size_t)BATCH * NPIX];        // pooled attention map (fp32)

// bf16 hi/lo split operands
__device__ __align__(128) bf16 g_fcH [(size_t)C2 * KCONV];   // fc0 permuted: k=(kh*3+kw)*2048+ci
__device__ __align__(128) bf16 g_fcL [(size_t)C2 * KCONV];
__device__ __align__(128) bf16 g_c4H [(size_t)C1 * K4];
__device__ __align__(128) bf16 g_c4L [(size_t)C1 * K4];
__device__ __align__(128) bf16 g_r5PH[(size_t)BATCH * 256 * C1];  // padded transpose [b][16][16][c]
__device__ __align__(128) bf16 g_r5PL[(size_t)BATCH * 256 * C1];
__device__ __align__(128) bf16 g_x1TH[(size_t)BATCH * NPIX * K4]; // [col][kc]
__device__ __align__(128) bf16 g_x1TL[(size_t)BATCH * NPIX * K4];
__device__ __align__(128) bf16 g_tTH [(size_t)BATCH * NPIX * C1]; // [col][c]
__device__ __align__(128) bf16 g_tTL [(size_t)BATCH * NPIX * C1];

// ===========================================================================
// helpers
// ===========================================================================
__device__ __forceinline__ void mma_bf16(float* d, const uint32_t* a, const uint32_t* b)
{
    asm volatile(
        "mma.sync.aligned.m16n8k16.row.col.f32.bf16.bf16.f32 "
        "{%0,%1,%2,%3}, {%4,%5,%6,%7}, {%8,%9}, {%0,%1,%2,%3};"
        : "+f"(d[0]), "+f"(d[1]), "+f"(d[2]), "+f"(d[3])
        : "r"(a[0]), "r"(a[1]), "r"(a[2]), "r"(a[3]), "r"(b[0]), "r"(b[1]));
}
__device__ __forceinline__ uint32_t lds32(const bf16* base, int elem)
{
    return *(const uint32_t*)(base + elem);
}
__device__ __forceinline__ void fsplit(float v, bf16& h, bf16& l)
{
    h = __float2bfloat16(v);
    l = __float2bfloat16(v - __bfloat162float(h));
}
__device__ __forceinline__ uint32_t smem_u32(const void* p) {
    uint32_t a;
    asm("{ .reg .u64 t; cvta.to.shared.u64 t, %1; cvt.u32.u64 %0, t; }" : "=r"(a) : "l"(p));
    return a;
}
__device__ __forceinline__ void cpa16(uint32_t dst, const void* src) {
    asm volatile("cp.async.cg.shared.global [%0], [%1], 16;" :: "r"(dst), "l"(src));
}
__device__ __forceinline__ void cpa_commit() {
    asm volatile("cp.async.commit_group;" ::: "memory");
}

// ===========================================================================
// prep kernels
// ===========================================================================
__global__ void cvt_split_kernel(const float* __restrict__ src, bf16* __restrict__ h,
                                 bf16* __restrict__ l, size_t n)
{
    for (size_t i = (size_t)blockIdx.x * blockDim.x + threadIdx.x; i < n;
         i += (size_t)gridDim.x * blockDim.x) {
        bf16 hh, ll;
        fsplit(src[i], hh, ll);
        h[i] = hh; l[i] = ll;
    }
}

// fc0 [m][ci*9 + kh*3 + kw] -> g_fc [m][(kh*3+kw)*2048 + ci] (split)
__global__ void fc0_perm_kernel(const float* __restrict__ src)
{
    for (size_t i = (size_t)blockIdx.x * blockDim.x + threadIdx.x;
         i < (size_t)C2 * KCONV; i += (size_t)gridDim.x * blockDim.x) {
        size_t m = i / KCONV;
        int kk = (int)(i - m * KCONV);
        int s = kk >> 11, ci = kk & 2047;
        bf16 hh, ll;
        fsplit(src[m * KCONV + (size_t)ci * 9 + s], hh, ll);
        g_fcH[i] = hh; g_fcL[i] = ll;
    }
}

// zero-fill padded r5P (both hi and lo), uint2 = 4 bf16 per store
__global__ void r5P_zero_kernel()
{
    size_t n4 = (size_t)BATCH * 256 * C1 / 4;
    uint2 z = make_uint2(0u, 0u);
    uint2* ph = (uint2*)g_r5PH;
    uint2* pl = (uint2*)g_r5PL;
    for (size_t i = (size_t)blockIdx.x * blockDim.x + threadIdx.x; i < n4;
         i += (size_t)gridDim.x * blockDim.x) {
        ph[i] = z; pl[i] = z;
    }
}

// interior fill: r5 [b][c][n] -> r5P [b][h+1][w+1][c] (transpose via smem tile)
__global__ void r5P_fill_kernel(const float* __restrict__ r5)
{
    __shared__ float tile[32][33];
    const int b = blockIdx.x, c0 = blockIdx.y * 32, n0 = blockIdx.z * 32;
    const int tx = threadIdx.x, ty = threadIdx.y;   // 32 x 8
#pragma unroll
    for (int j = 0; j < 4; j++) {
        int c = c0 + ty + j * 8, n = n0 + tx;
        if (n < NPIX) tile[ty + j * 8][tx] = r5[((size_t)b * C1 + c) * NPIX + n];
    }
    __syncthreads();
#pragma unroll
    for (int j = 0; j < 4; j++) {
        int n = n0 + ty + j * 8, c = c0 + tx;
        if (n < NPIX) {
            int h = n / 14, w = n - h * 14;
            bf16 hh, ll;
            fsplit(tile[tx][ty + j * 8], hh, ll);
            size_t o = (((size_t)b * 16 + h + 1) * 16 + (w + 1)) * C1 + c;
            g_r5PH[o] = hh; g_r5PL[o] = ll;
        }
    }
}

// ===========================================================================
// Unified tensor-core GEMM: block 128x128, chunk 32, 4-stage cp.async pipeline
// 512 threads / 16 warps, each warp computes 32x32.
// MODE 0: A=c4w,  B=x1T,             out tT = r5*(acc+bias)  (bf16 split)
// MODE 1: A=c4w,  B=[tT;r5P-center], out g_xb = acc+bias     (fp32)
// MODE 2: A=fc0P, B=shifted r5P,     out g_x = relu(BN(acc)) (fp32)
// ===========================================================================
#define SROW 40
#define MATE (128 * SROW)     // 5120 elems per matrix tile (10240 B)
#define STGE (4 * MATE)       // 20480 elems per stage
#define STGB (STGE * 2)       // 40960 bytes per stage
#define NSTG 4
#define SM_BYTES (NSTG * STGB)  // 163840

template <int MODE>
__global__ void __launch_bounds__(512, 1) mma_gemm_kernel(
    const bf16* __restrict__ Ah, const bf16* __restrict__ Al,
    const float* __restrict__ r5, const float* __restrict__ bias,
    const float* __restrict__ gamma, const float* __restrict__ beta,
    const float* __restrict__ mean,  const float* __restrict__ var)
{
    constexpr int KTOT = (MODE == 2) ? KCONV : K4;
    constexpr int NC = KTOT / 32;

    extern __shared__ bf16 sm[];
    const uint32_t sb = smem_u32(sm);

    const int tid = threadIdx.x;
    const int wid = tid >> 5, lane = tid & 31;
    const int g = lane >> 2, t4 = lane & 3;
    const int warp_m = wid >> 2, warp_n = wid & 3;   // 4 x 4 warp grid, 32x32 each
    const int m0 = blockIdx.y * 128, col0 = blockIdx.x * 128;

    // loader mapping: thread -> (matrix = tid>>7 in {Ah,Al,Bh,Bl}, row = tid&127)
    const int mt   = tid >> 7;
    const int rowL = tid & 127;
    const size_t aOfs = (size_t)(m0 + rowL) * KTOT;   // for mt 0/1
    const int colL = col0 + rowL;                      // for mt 2/3
    const int bB = colL / NPIX, pB = colL - bB * NPIX;
    const int hB = pB / 14, wB = pB - hB * 14;

    // global row base for this loader thread (16B-granule source)
    const bf16* gsrcA = (mt == 0 ? Ah : Al) + aOfs;                 // valid for mt<2
    const bf16* bH0;
    if (MODE == 0) bH0 = (mt == 2 ? g_x1TH : g_x1TL) + (size_t)colL * K4;
    else           bH0 = (mt == 2 ? g_tTH  : g_tTL ) + (size_t)colL * C1;
    const size_t padBase = (((size_t)bB * 16 + hB) * 16 + wB) * C1;
    const bf16* pP = (mt == 2 ? g_r5PH : g_r5PL) + padBase;

    const uint32_t dBase = sb + (uint32_t)mt * (MATE * 2) + (uint32_t)rowL * (SROW * 2);

    auto load_stage = [&](int st, int k0) {
        uint32_t d = dBase + st * STGB;
        const bf16* src;
        if (mt < 2) {
            src = gsrcA + k0;
        } else if (MODE == 0) {
            src = bH0 + k0;
        } else if (MODE == 1) {
            if (k0 < 2048) src = bH0 + k0;
            else           src = pP + (size_t)(1 * 16 + 1) * C1 + (k0 - 2048);
        } else {
            int s = k0 >> 11, coff = k0 & 2047;
            int kh = s / 3, kw = s - kh * 3;
            src = pP + (size_t)(kh * 16 + kw) * C1 + coff;
        }
        cpa16(d,      src);
        cpa16(d + 16, src + 8);
        cpa16(d + 32, src + 16);
        cpa16(d + 48, src + 24);
        cpa_commit();
    };

    float acc[2][4][4];
#pragma unroll
    for (int i = 0; i < 2; i++)
#pragma unroll
        for (int j = 0; j < 4; j++)
#pragma unroll
            for (int u = 0; u < 4; u++) acc[i][j][u] = 0.f;

    // prologue: 3 stages in flight
    load_stage(0, 0);
    load_stage(1, 32);
    load_stage(2, 64);

    for (int c = 0; c < NC; c++) {
        asm volatile("cp.async.wait_group 2;" ::: "memory");
        __syncthreads();   // publishes stage c; also proves compute(c-1) finished
        if (c + 3 < NC) load_stage((c + 3) & (NSTG - 1), (c + 3) * 32);
        else            cpa_commit();   // empty group keeps count uniform

        const bf16* pAh = sm + (size_t)(c & (NSTG - 1)) * STGE;
        const bf16* pAl = pAh + MATE;
        const bf16* pBh = pAh + 2 * MATE;
        const bf16* pBl = pAh + 3 * MATE;

#pragma unroll
        for (int kk = 0; kk < 32; kk += 16) {
            uint32_t aH[2][4], aL[2][4], bH[4][2], bL[4][2];
#pragma unroll
            for (int fm = 0; fm < 2; fm++) {
                int rb = (warp_m * 32 + fm * 16 + g) * SROW + kk + 2 * t4;
                aH[fm][0] = lds32(pAh, rb);
                aH[fm][1] = lds32(pAh, rb + 8 * SROW);
                aH[fm][2] = lds32(pAh, rb + 8);
                aH[fm][3] = lds32(pAh, rb + 8 * SROW + 8);
                aL[fm][0] = lds32(pAl, rb);
                aL[fm][1] = lds32(pAl, rb + 8 * SROW);
                aL[fm][2] = lds32(pAl, rb + 8);
                aL[fm][3] = lds32(pAl, rb + 8 * SROW + 8);
            }
#pragma unroll
            for (int fn = 0; fn < 4; fn++) {
                int nb = (warp_n * 32 + fn * 8 + g) * SROW + kk + 2 * t4;
                bH[fn][0] = lds32(pBh, nb);
                bH[fn][1] = lds32(pBh, nb + 8);
                bL[fn][0] = lds32(pBl, nb);
                bL[fn][1] = lds32(pBl, nb + 8);
            }
#pragma unroll
            for (int fm = 0; fm < 2; fm++)
#pragma unroll
                for (int fn = 0; fn < 4; fn++) {
                    mma_bf16(acc[fm][fn], aH[fm], bH[fn]);
                    mma_bf16(acc[fm][fn], aH[fm], bL[fn]);
                    mma_bf16(acc[fm][fn], aL[fm], bH[fn]);
                }
        }
    }

    // ---- epilogue ----
    float sc[2][2], sh[2][2];
#pragma unroll
    for (int fm = 0; fm < 2; fm++)
#pragma unroll
        for (int hf = 0; hf < 2; hf++) {
            int m = m0 + warp_m * 32 + fm * 16 + g + hf * 8;
            if (MODE == 2) {
                float s = gamma[m] / sqrtf(var[m] + 1e-5f);
                sc[fm][hf] = s;
                sh[fm][hf] = beta[m] - mean[m] * s;
            } else {
                sc[fm][hf] = 1.f;
                sh[fm][hf] = bias[m];
            }
        }
#pragma unroll
    for (int fm = 0; fm < 2; fm++) {
#pragma unroll
        for (int fn = 0; fn < 4; fn++) {
#pragma unroll
            for (int u = 0; u < 4; u++) {
                int hf = u >> 1;
                int m = m0 + warp_m * 32 + fm * 16 + g + hf * 8;
                int col = col0 + warp_n * 32 + fn * 8 + 2 * t4 + (u & 1);
                int bo = col / NPIX, n = col - bo * NPIX;
                float vv = acc[fm][fn][u] * sc[fm][hf] + sh[fm][hf];
                if (MODE == 2) {
                    g_x[((size_t)bo * C2 + m) * NPIX + n] = fmaxf(vv, 0.f);
                } else if (MODE == 1) {
                    g_xb[((size_t)bo * C1 + m) * NPIX + n] = vv;
                } else {
                    float tv = r5[((size_t)bo * C1 + m) * NPIX + n] * vv;
                    bf16 hh, ll;
                    fsplit(tv, hh, ll);
                    size_t o = (size_t)col * C1 + m;
                    g_tTH[o] = hh; g_tTL[o] = ll;
                }
            }
        }
    }
}

// ===========================================================================
// EM attention (stage_num=3), one block per batch
// ===========================================================================
__global__ void __launch_bounds__(256) em_kernel(const float* __restrict__ mu0)
{
    const int b = blockIdx.x;
    const int tid = threadIdx.x, lane = tid & 31, wid = tid >> 5;
    const float* xb = g_x + (size_t)b * C2 * NPIX;

    __shared__ float mu[C2 * 8];
    __shared__ float z[NPIX * 8];
    __shared__ float norm[8], colsum[8];

    {
        float s = 0.f;
        for (int c = lane; c < C2; c += 32) { float v = mu0[c * 8 + wid]; s += v * v; }
#pragma unroll
        for (int o = 16; o; o >>= 1) s += __shfl_xor_sync(0xffffffffu, s, o);
        if (!lane) norm[wid] = sqrtf(s) + EPSF;
    }
    __syncthreads();
    for (int i = tid; i < C2 * 8; i += 256) mu[i] = mu0[i] / norm[i & 7];
    __syncthreads();

    for (int it = 0; it < 3; ++it) {
        if (tid < NPIX) {
            float l[8];
#pragma unroll
            for (int k = 0; k < 8; k++) l[k] = 0.f;
            for (int c = 0; c < C2; c++) {
                float xv = xb[c * NPIX + tid];
#pragma unroll
                for (int k = 0; k < 8; k++) l[k] += xv * mu[c * 8 + k];
            }
            float mx = l[0];
#pragma unroll
            for (int k = 1; k < 8; k++) mx = fmaxf(mx, l[k]);
            float e[8], s = 0.f;
#pragma unroll
            for (int k = 0; k < 8; k++) { e[k] = expf(l[k] - mx); s += e[k]; }
            float inv = 1.f / s;
#pragma unroll
            for (int k = 0; k < 8; k++) z[tid * 8 + k] = e[k] * inv;
        }
        __syncthreads();
        {
            float s = 0.f;
            for (int n = lane; n < NPIX; n += 32) s += z[n * 8 + wid];
#pragma unroll
            for (int o = 16; o; o >>= 1) s += __shfl_xor_sync(0xffffffffu, s, o);
            if (!lane) colsum[wid] = s + EPSF;
        }
        __syncthreads();
        for (int o = tid; o < C2 * 8; o += 256) {
            int c = o >> 3, k = o & 7;
            const float* xr = xb + c * NPIX;
            float s = 0.f;
            for (int n = 0; n < NPIX; n++) s += xr[n] * z[n * 8 + k];
            mu[o] = s / colsum[k];
        }
        __syncthreads();
        {
            float s = 0.f;
            for (int c = lane; c < C2; c += 32) { float v = mu[c * 8 + wid]; s += v * v; }
#pragma unroll
            for (int o = 16; o; o >>= 1) s += __shfl_xor_sync(0xffffffffu, s, o);
            if (!lane) norm[wid] = sqrtf(s) + EPSF;
        }
        __syncthreads();
        for (int i = tid; i < C2 * 8; i += 256) mu[i] /= norm[i & 7];
        __syncthreads();
    }
    if (tid < NPIX) {
        float zr[8];
#pragma unroll
        for (int k = 0; k < 8; k++) zr[k] = z[tid * 8 + k];
        float* x2o = g_x2 + (size_t)b * C2 * NPIX;
        for (int c = 0; c < C2; c++) {
            float s = 0.f;
#pragma unroll
            for (int k = 0; k < 8; k++) s += mu[c * 8 + k] * zr[k];
            float v = xb[c * NPIX + tid] + s;
            x2o[c * NPIX + tid] = fmaxf(v, 0.f);
        }
#pragma unroll
        for (int k = 0; k < 8; k++) g_zt[((size_t)b * 8 + k) * NPIX + tid] = zr[k];
    }
}

// ===========================================================================
// x1T: x1T[(b*196+h*14+v)][k*512+c] = sum_w x2[b,c,h*14+w] * zt[b,k,w*14+v]
// ===========================================================================
__global__ void __launch_bounds__(256) x1T_kernel()
{
    const int b = blockIdx.x, h = blockIdx.y;
    const int tid = threadIdx.x, lane = tid & 31, wid = tid >> 5;

    __shared__ float x2s[C2 * 14];
    __shared__ float zts[8 * NPIX];
    for (int i = tid; i < C2 * 14; i += 256) {
        int c = i / 14, w = i - c * 14;
        x2s[i] = g_x2[((size_t)b * C2 + c) * NPIX + h * 14 + w];
    }
    for (int i = tid; i < 8 * NPIX; i += 256) zts[i] = g_zt[(size_t)b * 8 * NPIX + i];
    __syncthreads();

    for (int ci = 0; ci < 2; ci++) {
        const int c = wid * 64 + ci * 32 + lane;
        float xv[14];
#pragma unroll
        for (int w = 0; w < 14; w++) xv[w] = x2s[c * 14 + w];
#pragma unroll
        for (int k = 0; k < 8; k++) {
            float out[14];
#pragma unroll
            for (int v = 0; v < 14; v++) out[v] = 0.f;
#pragma unroll
            for (int w = 0; w < 14; w++) {
                float a = xv[w];
                const float* zp = zts + k * NPIX + w * 14;
#pragma unroll
                for (int v = 0; v < 14; v++) out[v] += a * zp[v];
            }
#pragma unroll
            for (int v = 0; v < 14; v++) {
                bf16 hh, ll;
                fsplit(out[v], hh, ll);
                size_t o = ((size_t)b * NPIX + h * 14 + v) * K4 + k * C2 + c;
                g_x1TH[o] = hh; g_x1TL[o] = ll;
            }
        }
    }
}

// ===========================================================================
// downconv 2048->32 (16 output channels per block, dynamic smem weights)
// ===========================================================================
__global__ void __launch_bounds__(256) down_kernel(
    const float* __restrict__ dw, const float* __restrict__ db)
{
    extern __shared__ float ws[];     // 16 * 2048 floats
    const int b = blockIdx.x, jg = blockIdx.y, tid = threadIdx.x;
    for (int i = tid; i < 16 * 2048; i += 256) ws[i] = dw[jg * 16 * 2048 + i];
    __syncthreads();
    if (tid < NPIX) {
        float acc[16];
#pragma unroll
        for (int j = 0; j < 16; j++) acc[j] = db[jg * 16 + j];
        const float* xp = g_xb + (size_t)b * C1 * NPIX + tid;
        for (int c = 0; c < 2048; c++) {
            float v = xp[(size_t)c * NPIX];
#pragma unroll
            for (int j = 0; j < 16; j++) acc[j] += ws[j * 2048 + c] * v;
        }
#pragma unroll
        for (int j = 0; j < 16; j++)
            g_xd[((size_t)b * 32 + jg * 16 + j) * NPIX + tid] = acc[j];
    }
}
#define DOWN_SMEM (16 * 2048 * 4)

// ===========================================================================
// GAP + class-wise pools -> xg (output[0:512]) and xc map
// ===========================================================================
__global__ void __launch_bounds__(256) pool_kernel(float* __restrict__ dout)
{
    const int b = blockIdx.x, tid = threadIdx.x;
    __shared__ float gap[32];
    __shared__ float xgs[8];
    if (tid < 32) {
        const float* p = g_xd + ((size_t)b * 32 + tid) * NPIX;
        float s = 0.f;
        for (int n = 0; n < NPIX; n++) s += p[n];
        gap[tid] = s * (1.f / NPIX);
    }
    __syncthreads();
    if (tid < 8) {
        float g = 0.25f * (gap[4 * tid] + gap[4 * tid + 1] + gap[4 * tid + 2] + gap[4 * tid + 3]);
        xgs[tid] = g;
        dout[b * 8 + tid] = g;
    }
    __syncthreads();
    if (tid < NPIX) {
        const float* p = g_xd + (size_t)b * 32 * NPIX + tid;
        float s = 0.f;
#pragma unroll
        for (int pp = 0; pp < 8; pp++) {
            float cp = 0.25f * (p[(4 * pp + 0) * NPIX] + p[(4 * pp + 1) * NPIX] +
                                p[(4 * pp + 2) * NPIX] + p[(4 * pp + 3) * NPIX]);
            s += cp * xgs[pp];
        }
        g_xc[b * NPIX + tid] = s * 0.125f;
    }
}

// ===========================================================================
// cls head -> out2 (output[512:1024])
// ===========================================================================
__global__ void __launch_bounds__(256) out2_kernel(
    const float* __restrict__ r5, const float* __restrict__ cw,
    const float* __restrict__ cb, float* __restrict__ dout)
{
    const int b = blockIdx.x, tid = threadIdx.x, lane = tid & 31, wid = tid >> 5;
    __shared__ float xcs[NPIX];
    for (int i = tid; i < NPIX; i += 256) xcs[i] = g_xc[b * NPIX + i];
    __syncthreads();
    const float inv = 1.f / NPIX;
    float accL = 0.f;
    for (int c = wid; c < 2048; c += 8) {
        const float* rp = r5 + ((size_t)b * C1 + c) * NPIX;
        float s1 = 0.f, s2 = 0.f;
        for (int n = lane; n < NPIX; n += 32) { float v = rp[n]; s1 += v; s2 += v * xcs[n]; }
#pragma unroll
        for (int o = 16; o; o >>= 1) {
            s1 += __shfl_xor_sync(0xffffffffu, s1, o);
            s2 += __shfl_xor_sync(0xffffffffu, s2, o);
        }
        if (lane < 8)
            accL += cw[lane * 4096 + c] * s1 * inv + cw[lane * 4096 + 2048 + c] * s2 * inv;
    }
    __shared__ float wsum[8][8];
    if (lane < 8) wsum[wid][lane] = accL;
    __syncthreads();
    if (tid < 8) {
        float s = cb[tid];
#pragma unroll
        for (int w2 = 0; w2 < 8; w2++) s += wsum[w2][tid];
        dout[512 + b * 8 + tid] = s;
    }
}

// ===========================================================================
extern "C" void kernel_launch(void* const* d_in, const int* in_sizes, int n_in,
                              void* d_out, int out_size)
{
    const float* r5   = (const float*)d_in[0];
    const float* fc0  = (const float*)d_in[1];
    const float* bng  = (const float*)d_in[2];
    const float* bnb  = (const float*)d_in[3];
    const float* bnm  = (const float*)d_in[4];
    const float* bnv  = (const float*)d_in[5];
    const float* mu0  = (const float*)d_in[6];
    const float* c4w  = (const float*)d_in[7];
    const float* c4b  = (const float*)d_in[8];
    const float* dw   = (const float*)d_in[9];
    const float* db   = (const float*)d_in[10];
    const float* cw   = (const float*)d_in[11];
    const float* cb   = (const float*)d_in[12];
    float* out = (float*)d_out;

    static int smem_set = 0;
    if (!smem_set) {
        cudaFuncSetAttribute(mma_gemm_kernel<0>, cudaFuncAttributeMaxDynamicSharedMemorySize, SM_BYTES);
        cudaFuncSetAttribute(mma_gemm_kernel<1>, cudaFuncAttributeMaxDynamicSharedMemorySize, SM_BYTES);
        cudaFuncSetAttribute(mma_gemm_kernel<2>, cudaFuncAttributeMaxDynamicSharedMemorySize, SM_BYTES);
        cudaFuncSetAttribute(down_kernel, cudaFuncAttributeMaxDynamicSharedMemorySize, DOWN_SMEM);
        smem_set = 1;
    }

    bf16 *fcH, *fcL, *c4H, *c4L;
    cudaGetSymbolAddress((void**)&fcH, g_fcH);
    cudaGetSymbolAddress((void**)&fcL, g_fcL);
    cudaGetSymbolAddress((void**)&c4H, g_c4H);
    cudaGetSymbolAddress((void**)&c4L, g_c4L);

    // ---- prep for conv (launch order keeps conv GEMM at slot #4 for ncu) ----
    fc0_perm_kernel<<<2048, 256>>>(fc0);
    r5P_zero_kernel<<<1024, 256>>>();
    r5P_fill_kernel<<<dim3(64, 64, 7), dim3(32, 8)>>>(r5);

    // ---- conv3x3 + BN + ReLU (launch #4 -> profiled) ----
    mma_gemm_kernel<2><<<dim3(98, 4), 512, SM_BYTES>>>(fcH, fcL, r5, nullptr, bng, bnb, bnm, bnv);

    // c4 weight split only needed before conv4 passes
    cvt_split_kernel<<<2048, 256>>>(c4w, c4H, c4L, (size_t)C1 * K4);
    em_kernel<<<64, 256>>>(mu0);
    x1T_kernel<<<dim3(64, 14), 256>>>();

    // ---- conv4 pass 1 & 2 ----
    mma_gemm_kernel<0><<<dim3(98, 16), 512, SM_BYTES>>>(c4H, c4L, r5, c4b, nullptr, nullptr, nullptr, nullptr);
    mma_gemm_kernel<1><<<dim3(98, 16), 512, SM_BYTES>>>(c4H, c4L, r5, c4b, nullptr, nullptr, nullptr, nullptr);
    down_kernel<<<dim3(64, 2), 256, DOWN_SMEM>>>(dw, db);
    pool_kernel<<<64, 256>>>(out);
    out2_kernel<<<64, 256>>>(r5, cw, cb, out);
}

// round 11
// speedup vs baseline: 1.0386x; 1.0386x over previous
#include <cuda_runtime.h>
#include <cuda_bf16.h>
#include <cstdint>

#define BATCH 64
#define NPIX  196
#define C1    2048
#define C2    512
#define KCONV 18432
#define K4    4096
#define EPSF  1e-6f

typedef __nv_bfloat16 bf16;

// ---------------- scratch (device globals; no allocation) ----------------
__device__ float g_x [(size_t)BATCH * C2 * NPIX];   // conv+bn+relu output (fp32)
__device__ float g_x2[(size_t)BATCH * C2 * NPIX];   // GCEM output (fp32)
__device__ float g_zt[(size_t)BATCH * 8  * NPIX];   // attention maps (fp32)
__device__ float g_xb[(size_t)BATCH * C1 * NPIX];   // conv4(concat) output (fp32)
__device__ float g_xd[(size_t)BATCH * 32 * NPIX];   // downconv (fp32)
__device__ float g_xc[(size_t)BATCH * NPIX];        // pooled attention map (fp32)

// bf16 hi/lo split operands
__device__ __align__(128) bf16 g_fcH [(size_t)C2 * KCONV];   // fc0 permuted: k=(kh*3+kw)*2048+ci
__device__ __align__(128) bf16 g_fcL [(size_t)C2 * KCONV];
__device__ __align__(128) bf16 g_c4H [(size_t)C1 * K4];
__device__ __align__(128) bf16 g_c4L [(size_t)C1 * K4];
__device__ __align__(128) bf16 g_r5PH[(size_t)BATCH * 256 * C1];  // padded transpose [b][16][16][c]
__device__ __align__(128) bf16 g_r5PL[(size_t)BATCH * 256 * C1];
__device__ __align__(128) bf16 g_x1TH[(size_t)BATCH * NPIX * K4]; // [col][kc]
__device__ __align__(128) bf16 g_x1TL[(size_t)BATCH * NPIX * K4];
__device__ __align__(128) bf16 g_tTH [(size_t)BATCH * NPIX * C1]; // [col][c]
__device__ __align__(128) bf16 g_tTL [(size_t)BATCH * NPIX * C1];

// ===========================================================================
// helpers
// ===========================================================================
__device__ __forceinline__ void mma_bf16(float* d, const uint32_t* a, const uint32_t* b)
{
    asm volatile(
        "mma.sync.aligned.m16n8k16.row.col.f32.bf16.bf16.f32 "
        "{%0,%1,%2,%3}, {%4,%5,%6,%7}, {%8,%9}, {%0,%1,%2,%3};"
        : "+f"(d[0]), "+f"(d[1]), "+f"(d[2]), "+f"(d[3])
        : "r"(a[0]), "r"(a[1]), "r"(a[2]), "r"(a[3]), "r"(b[0]), "r"(b[1]));
}
__device__ __forceinline__ uint32_t lds32(const bf16* base, int elem)
{
    return *(const uint32_t*)(base + elem);
}
__device__ __forceinline__ void fsplit(float v, bf16& h, bf16& l)
{
    h = __float2bfloat16(v);
    l = __float2bfloat16(v - __bfloat162float(h));
}
__device__ __forceinline__ uint32_t smem_u32(const void* p) {
    uint32_t a;
    asm("{ .reg .u64 t; cvta.to.shared.u64 t, %1; cvt.u32.u64 %0, t; }" : "=r"(a) : "l"(p));
    return a;
}
__device__ __forceinline__ void cpa16(uint32_t dst, const void* src) {
    asm volatile("cp.async.cg.shared.global [%0], [%1], 16;" :: "r"(dst), "l"(src));
}
__device__ __forceinline__ void cpa_commit() {
    asm volatile("cp.async.commit_group;" ::: "memory");
}

// ===========================================================================
// prep kernels
// ===========================================================================
__global__ void cvt_split_kernel(const float* __restrict__ src, bf16* __restrict__ h,
                                 bf16* __restrict__ l, size_t n)
{
    for (size_t i = (size_t)blockIdx.x * blockDim.x + threadIdx.x; i < n;
         i += (size_t)gridDim.x * blockDim.x) {
        bf16 hh, ll;
        fsplit(src[i], hh, ll);
        h[i] = hh; l[i] = ll;
    }
}

// fc0 [m][ci*9 + kh*3 + kw] -> g_fc [m][(kh*3+kw)*2048 + ci] (split)
__global__ void fc0_perm_kernel(const float* __restrict__ src)
{
    for (size_t i = (size_t)blockIdx.x * blockDim.x + threadIdx.x;
         i < (size_t)C2 * KCONV; i += (size_t)gridDim.x * blockDim.x) {
        size_t m = i / KCONV;
        int kk = (int)(i - m * KCONV);
        int s = kk >> 11, ci = kk & 2047;
        bf16 hh, ll;
        fsplit(src[m * KCONV + (size_t)ci * 9 + s], hh, ll);
        g_fcH[i] = hh; g_fcL[i] = ll;
    }
}

// zero-fill padded r5P (both hi and lo), uint2 = 4 bf16 per store
__global__ void r5P_zero_kernel()
{
    size_t n4 = (size_t)BATCH * 256 * C1 / 4;
    uint2 z = make_uint2(0u, 0u);
    uint2* ph = (uint2*)g_r5PH;
    uint2* pl = (uint2*)g_r5PL;
    for (size_t i = (size_t)blockIdx.x * blockDim.x + threadIdx.x; i < n4;
         i += (size_t)gridDim.x * blockDim.x) {
        ph[i] = z; pl[i] = z;
    }
}

// interior fill: r5 [b][c][n] -> r5P [b][h+1][w+1][c] (transpose via smem tile)
__global__ void r5P_fill_kernel(const float* __restrict__ r5)
{
    __shared__ float tile[32][33];
    const int b = blockIdx.x, c0 = blockIdx.y * 32, n0 = blockIdx.z * 32;
    const int tx = threadIdx.x, ty = threadIdx.y;   // 32 x 8
#pragma unroll
    for (int j = 0; j < 4; j++) {
        int c = c0 + ty + j * 8, n = n0 + tx;
        if (n < NPIX) tile[ty + j * 8][tx] = r5[((size_t)b * C1 + c) * NPIX + n];
    }
    __syncthreads();
#pragma unroll
    for (int j = 0; j < 4; j++) {
        int n = n0 + ty + j * 8, c = c0 + tx;
        if (n < NPIX) {
            int h = n / 14, w = n - h * 14;
            bf16 hh, ll;
            fsplit(tile[tx][ty + j * 8], hh, ll);
            size_t o = (((size_t)b * 16 + h + 1) * 16 + (w + 1)) * C1 + c;
            g_r5PH[o] = hh; g_r5PL[o] = ll;
        }
    }
}

// ===========================================================================
// Unified tensor-core GEMM: block 128(M)x256(N), chunk 32, 3-stage cp.async
// 256 threads / 8 warps in 2(m) x 4(n) grid; each warp computes 64x64.
// MODE 0: A=c4w,  B=x1T,             out tT = r5*(acc+bias)  (bf16 split)
// MODE 1: A=c4w,  B=[tT;r5P-center], out g_xb = acc+bias     (fp32)
// MODE 2: A=fc0P, B=shifted r5P,     out g_x = relu(BN(acc)) (fp32)
// ===========================================================================
#define SROW 40
#define OFF_AH 0
#define OFF_AL 5120           // 128*40
#define OFF_BH 10240          // 256*40
#define OFF_BL 20480          // 512*40
#define STGE   30720          // 768*40 elems per stage
#define STGB   (STGE * 2)     // 61440 bytes per stage
#define NSTG   3
#define SM_BYTES (NSTG * STGB)  // 184320

template <int MODE>
__global__ void __launch_bounds__(256, 1) mma_gemm_kernel(
    const bf16* __restrict__ Ah, const bf16* __restrict__ Al,
    const float* __restrict__ r5, const float* __restrict__ bias,
    const float* __restrict__ gamma, const float* __restrict__ beta,
    const float* __restrict__ mean,  const float* __restrict__ var)
{
    constexpr int KTOT = (MODE == 2) ? KCONV : K4;
    constexpr int NC = KTOT / 32;

    extern __shared__ bf16 sm[];
    const uint32_t sb = smem_u32(sm);

    const int tid = threadIdx.x;
    const int wid = tid >> 5, lane = tid & 31;
    const int g = lane >> 2, t4 = lane & 3;
    const int warp_m = wid >> 2, warp_n = wid & 3;   // 2 x 4 warp grid, 64x64 each
    const int m0 = blockIdx.y * 128, col0 = blockIdx.x * 256;

    // ---- loader mapping: thread t owns A-row (hi t<128 / lo t>=128) + B cols ----
    const int aRow = tid & 127;
    const bf16* gA = (tid < 128 ? Ah : Al) + (size_t)(m0 + aRow) * KTOT;

    const int colL = col0 + tid;              // B column owned by this thread
    const int bB = colL / NPIX, pB = colL - bB * NPIX;
    const int hB = pB / 14, wB = pB - hB * 14;

    const bf16 *bHsrc0, *bLsrc0;
    if (MODE == 0) {
        bHsrc0 = g_x1TH + (size_t)colL * K4;
        bLsrc0 = g_x1TL + (size_t)colL * K4;
    } else {
        bHsrc0 = g_tTH + (size_t)colL * C1;   // MODE1 k<2048 part
        bLsrc0 = g_tTL + (size_t)colL * C1;
    }
    const size_t padBase = (((size_t)bB * 16 + hB) * 16 + wB) * C1;
    const bf16* pPH = g_r5PH + padBase;
    const bf16* pPL = g_r5PL + padBase;

    const uint32_t dA  = sb + ((tid < 128 ? OFF_AH : OFF_AL) + aRow * SROW) * 2;
    const uint32_t dBh = sb + (OFF_BH + tid * SROW) * 2;
    const uint32_t dBl = sb + (OFF_BL + tid * SROW) * 2;

    auto load_stage = [&](int st, int k0) {
        const uint32_t so = (uint32_t)st * STGB;
        const bf16* srcA = gA + k0;
        const bf16 *srcBh, *srcBl;
        if (MODE == 0) {
            srcBh = bHsrc0 + k0; srcBl = bLsrc0 + k0;
        } else if (MODE == 1) {
            if (k0 < 2048) { srcBh = bHsrc0 + k0; srcBl = bLsrc0 + k0; }
            else {
                size_t o = (size_t)(1 * 16 + 1) * C1 + (k0 - 2048);  // center shift
                srcBh = pPH + o; srcBl = pPL + o;
            }
        } else {
            int s = k0 >> 11, coff = k0 & 2047;
            int kh = s / 3, kw = s - kh * 3;
            size_t o = (size_t)(kh * 16 + kw) * C1 + coff;
            srcBh = pPH + o; srcBl = pPL + o;
        }
#pragma unroll
        for (int u = 0; u < 4; u++) {
            cpa16(dA  + so + u * 16, srcA  + u * 8);
            cpa16(dBh + so + u * 16, srcBh + u * 8);
            cpa16(dBl + so + u * 16, srcBl + u * 8);
        }
        cpa_commit();
    };

    float acc[4][8][4];
#pragma unroll
    for (int i = 0; i < 4; i++)
#pragma unroll
        for (int j = 0; j < 8; j++)
#pragma unroll
            for (int u = 0; u < 4; u++) acc[i][j][u] = 0.f;

    // prologue: 2 stages in flight
    load_stage(0, 0);
    load_stage(1, 32);

    int st = 0;   // stage index of chunk c (mod 3)
    for (int c = 0; c < NC; c++) {
        asm volatile("cp.async.wait_group 1;" ::: "memory");
        __syncthreads();   // publishes stage c; proves compute(c-1) done
        {
            int stn = st + 2; if (stn >= NSTG) stn -= NSTG;
            if (c + 2 < NC) load_stage(stn, (c + 2) * 32);
            else            cpa_commit();   // empty group keeps count uniform
        }

        const bf16* pAh = sm + (size_t)st * STGE + OFF_AH;
        const bf16* pAl = sm + (size_t)st * STGE + OFF_AL;
        const bf16* pBh = sm + (size_t)st * STGE + OFF_BH;
        const bf16* pBl = sm + (size_t)st * STGE + OFF_BL;

#pragma unroll
        for (int kk = 0; kk < 32; kk += 16) {
            uint32_t aH[4][4], aL[4][4], bH[8][2], bL[8][2];
#pragma unroll
            for (int fm = 0; fm < 4; fm++) {
                int rb = (warp_m * 64 + fm * 16 + g) * SROW + kk + 2 * t4;
                aH[fm][0] = lds32(pAh, rb);
                aH[fm][1] = lds32(pAh, rb + 8 * SROW);
                aH[fm][2] = lds32(pAh, rb + 8);
                aH[fm][3] = lds32(pAh, rb + 8 * SROW + 8);
                aL[fm][0] = lds32(pAl, rb);
                aL[fm][1] = lds32(pAl, rb + 8 * SROW);
                aL[fm][2] = lds32(pAl, rb + 8);
                aL[fm][3] = lds32(pAl, rb + 8 * SROW + 8);
            }
#pragma unroll
            for (int fn = 0; fn < 8; fn++) {
                int nb = (warp_n * 64 + fn * 8 + g) * SROW + kk + 2 * t4;
                bH[fn][0] = lds32(pBh, nb);
                bH[fn][1] = lds32(pBh, nb + 8);
                bL[fn][0] = lds32(pBl, nb);
                bL[fn][1] = lds32(pBl, nb + 8);
            }
#pragma unroll
            for (int fm = 0; fm < 4; fm++)
#pragma unroll
                for (int fn = 0; fn < 8; fn++) {
                    mma_bf16(acc[fm][fn], aH[fm], bH[fn]);
                    mma_bf16(acc[fm][fn], aH[fm], bL[fn]);
                    mma_bf16(acc[fm][fn], aL[fm], bH[fn]);
                }
        }
        if (++st == NSTG) st = 0;
    }

    // ---- epilogue ----
    float sc[4][2], sh[4][2];
#pragma unroll
    for (int fm = 0; fm < 4; fm++)
#pragma unroll
        for (int hf = 0; hf < 2; hf++) {
            int m = m0 + warp_m * 64 + fm * 16 + g + hf * 8;
            if (MODE == 2) {
                float s = gamma[m] / sqrtf(var[m] + 1e-5f);
                sc[fm][hf] = s;
                sh[fm][hf] = beta[m] - mean[m] * s;
            } else {
                sc[fm][hf] = 1.f;
                sh[fm][hf] = bias[m];
            }
        }
#pragma unroll
    for (int fm = 0; fm < 4; fm++) {
#pragma unroll
        for (int fn = 0; fn < 8; fn++) {
#pragma unroll
            for (int u = 0; u < 4; u++) {
                int hf = u >> 1;
                int m = m0 + warp_m * 64 + fm * 16 + g + hf * 8;
                int col = col0 + warp_n * 64 + fn * 8 + 2 * t4 + (u & 1);
                int bo = col / NPIX, n = col - bo * NPIX;
                float vv = acc[fm][fn][u] * sc[fm][hf] + sh[fm][hf];
                if (MODE == 2) {
                    g_x[((size_t)bo * C2 + m) * NPIX + n] = fmaxf(vv, 0.f);
                } else if (MODE == 1) {
                    g_xb[((size_t)bo * C1 + m) * NPIX + n] = vv;
                } else {
                    float tv = r5[((size_t)bo * C1 + m) * NPIX + n] * vv;
                    bf16 hh, ll;
                    fsplit(tv, hh, ll);
                    size_t o = (size_t)col * C1 + m;
                    g_tTH[o] = hh; g_tTL[o] = ll;
                }
            }
        }
    }
}

// ===========================================================================
// EM attention (stage_num=3), one block per batch
// ===========================================================================
__global__ void __launch_bounds__(256) em_kernel(const float* __restrict__ mu0)
{
    const int b = blockIdx.x;
    const int tid = threadIdx.x, lane = tid & 31, wid = tid >> 5;
    const float* xb = g_x + (size_t)b * C2 * NPIX;

    __shared__ float mu[C2 * 8];
    __shared__ float z[NPIX * 8];
    __shared__ float norm[8], colsum[8];

    {
        float s = 0.f;
        for (int c = lane; c < C2; c += 32) { float v = mu0[c * 8 + wid]; s += v * v; }
#pragma unroll
        for (int o = 16; o; o >>= 1) s += __shfl_xor_sync(0xffffffffu, s, o);
        if (!lane) norm[wid] = sqrtf(s) + EPSF;
    }
    __syncthreads();
    for (int i = tid; i < C2 * 8; i += 256) mu[i] = mu0[i] / norm[i & 7];
    __syncthreads();

    for (int it = 0; it < 3; ++it) {
        if (tid < NPIX) {
            float l[8];
#pragma unroll
            for (int k = 0; k < 8; k++) l[k] = 0.f;
            for (int c = 0; c < C2; c++) {
                float xv = xb[c * NPIX + tid];
#pragma unroll
                for (int k = 0; k < 8; k++) l[k] += xv * mu[c * 8 + k];
            }
            float mx = l[0];
#pragma unroll
            for (int k = 1; k < 8; k++) mx = fmaxf(mx, l[k]);
            float e[8], s = 0.f;
#pragma unroll
            for (int k = 0; k < 8; k++) { e[k] = expf(l[k] - mx); s += e[k]; }
            float inv = 1.f / s;
#pragma unroll
            for (int k = 0; k < 8; k++) z[tid * 8 + k] = e[k] * inv;
        }
        __syncthreads();
        {
            float s = 0.f;
            for (int n = lane; n < NPIX; n += 32) s += z[n * 8 + wid];
#pragma unroll
            for (int o = 16; o; o >>= 1) s += __shfl_xor_sync(0xffffffffu, s, o);
            if (!lane) colsum[wid] = s + EPSF;
        }
        __syncthreads();
        for (int o = tid; o < C2 * 8; o += 256) {
            int c = o >> 3, k = o & 7;
            const float* xr = xb + c * NPIX;
            float s = 0.f;
            for (int n = 0; n < NPIX; n++) s += xr[n] * z[n * 8 + k];
            mu[o] = s / colsum[k];
        }
        __syncthreads();
        {
            float s = 0.f;
            for (int c = lane; c < C2; c += 32) { float v = mu[c * 8 + wid]; s += v * v; }
#pragma unroll
            for (int o = 16; o; o >>= 1) s += __shfl_xor_sync(0xffffffffu, s, o);
            if (!lane) norm[wid] = sqrtf(s) + EPSF;
        }
        __syncthreads();
        for (int i = tid; i < C2 * 8; i += 256) mu[i] /= norm[i & 7];
        __syncthreads();
    }
    if (tid < NPIX) {
        float zr[8];
#pragma unroll
        for (int k = 0; k < 8; k++) zr[k] = z[tid * 8 + k];
        float* x2o = g_x2 + (size_t)b * C2 * NPIX;
        for (int c = 0; c < C2; c++) {
            float s = 0.f;
#pragma unroll
            for (int k = 0; k < 8; k++) s += mu[c * 8 + k] * zr[k];
            float v = xb[c * NPIX + tid] + s;
            x2o[c * NPIX + tid] = fmaxf(v, 0.f);
        }
#pragma unroll
        for (int k = 0; k < 8; k++) g_zt[((size_t)b * 8 + k) * NPIX + tid] = zr[k];
    }
}

// ===========================================================================
// x1T: x1T[(b*196+h*14+v)][k*512+c] = sum_w x2[b,c,h*14+w] * zt[b,k,w*14+v]
// ===========================================================================
__global__ void __launch_bounds__(256) x1T_kernel()
{
    const int b = blockIdx.x, h = blockIdx.y;
    const int tid = threadIdx.x, lane = tid & 31, wid = tid >> 5;

    __shared__ float x2s[C2 * 14];
    __shared__ float zts[8 * NPIX];
    for (int i = tid; i < C2 * 14; i += 256) {
        int c = i / 14, w = i - c * 14;
        x2s[i] = g_x2[((size_t)b * C2 + c) * NPIX + h * 14 + w];
    }
    for (int i = tid; i < 8 * NPIX; i += 256) zts[i] = g_zt[(size_t)b * 8 * NPIX + i];
    __syncthreads();

    for (int ci = 0; ci < 2; ci++) {
        const int c = wid * 64 + ci * 32 + lane;
        float xv[14];
#pragma unroll
        for (int w = 0; w < 14; w++) xv[w] = x2s[c * 14 + w];
#pragma unroll
        for (int k = 0; k < 8; k++) {
            float out[14];
#pragma unroll
            for (int v = 0; v < 14; v++) out[v] = 0.f;
#pragma unroll
            for (int w = 0; w < 14; w++) {
                float a = xv[w];
                const float* zp = zts + k * NPIX + w * 14;
#pragma unroll
                for (int v = 0; v < 14; v++) out[v] += a * zp[v];
            }
#pragma unroll
            for (int v = 0; v < 14; v++) {
                bf16 hh, ll;
                fsplit(out[v], hh, ll);
                size_t o = ((size_t)b * NPIX + h * 14 + v) * K4 + k * C2 + c;
                g_x1TH[o] = hh; g_x1TL[o] = ll;
            }
        }
    }
}

// ===========================================================================
// downconv 2048->32 (16 output channels per block, dynamic smem weights)
// ===========================================================================
__global__ void __launch_bounds__(256) down_kernel(
    const float* __restrict__ dw, const float* __restrict__ db)
{
    extern __shared__ float ws[];     // 16 * 2048 floats
    const int b = blockIdx.x, jg = blockIdx.y, tid = threadIdx.x;
    for (int i = tid; i < 16 * 2048; i += 256) ws[i] = dw[jg * 16 * 2048 + i];
    __syncthreads();
    if (tid < NPIX) {
        float acc[16];
#pragma unroll
        for (int j = 0; j < 16; j++) acc[j] = db[jg * 16 + j];
        const float* xp = g_xb + (size_t)b * C1 * NPIX + tid;
        for (int c = 0; c < 2048; c++) {
            float v = xp[(size_t)c * NPIX];
#pragma unroll
            for (int j = 0; j < 16; j++) acc[j] += ws[j * 2048 + c] * v;
        }
#pragma unroll
        for (int j = 0; j < 16; j++)
            g_xd[((size_t)b * 32 + jg * 16 + j) * NPIX + tid] = acc[j];
    }
}
#define DOWN_SMEM (16 * 2048 * 4)

// ===========================================================================
// GAP + class-wise pools -> xg (output[0:512]) and xc map
// ===========================================================================
__global__ void __launch_bounds__(256) pool_kernel(float* __restrict__ dout)
{
    const int b = blockIdx.x, tid = threadIdx.x;
    __shared__ float gap[32];
    __shared__ float xgs[8];
    if (tid < 32) {
        const float* p = g_xd + ((size_t)b * 32 + tid) * NPIX;
        float s = 0.f;
        for (int n = 0; n < NPIX; n++) s += p[n];
        gap[tid] = s * (1.f / NPIX);
    }
    __syncthreads();
    if (tid < 8) {
        float g = 0.25f * (gap[4 * tid] + gap[4 * tid + 1] + gap[4 * tid + 2] + gap[4 * tid + 3]);
        xgs[tid] = g;
        dout[b * 8 + tid] = g;
    }
    __syncthreads();
    if (tid < NPIX) {
        const float* p = g_xd + (size_t)b * 32 * NPIX + tid;
        float s = 0.f;
#pragma unroll
        for (int pp = 0; pp < 8; pp++) {
            float cp = 0.25f * (p[(4 * pp + 0) * NPIX] + p[(4 * pp + 1) * NPIX] +
                                p[(4 * pp + 2) * NPIX] + p[(4 * pp + 3) * NPIX]);
            s += cp * xgs[pp];
        }
        g_xc[b * NPIX + tid] = s * 0.125f;
    }
}

// ===========================================================================
// cls head -> out2 (output[512:1024])
// ===========================================================================
__global__ void __launch_bounds__(256) out2_kernel(
    const float* __restrict__ r5, const float* __restrict__ cw,
    const float* __restrict__ cb, float* __restrict__ dout)
{
    const int b = blockIdx.x, tid = threadIdx.x, lane = tid & 31, wid = tid >> 5;
    __shared__ float xcs[NPIX];
    for (int i = tid; i < NPIX; i += 256) xcs[i] = g_xc[b * NPIX + i];
    __syncthreads();
    const float inv = 1.f / NPIX;
    float accL = 0.f;
    for (int c = wid; c < 2048; c += 8) {
        const float* rp = r5 + ((size_t)b * C1 + c) * NPIX;
        float s1 = 0.f, s2 = 0.f;
        for (int n = lane; n < NPIX; n += 32) { float v = rp[n]; s1 += v; s2 += v * xcs[n]; }
#pragma unroll
        for (int o = 16; o; o >>= 1) {
            s1 += __shfl_xor_sync(0xffffffffu, s1, o);
            s2 += __shfl_xor_sync(0xffffffffu, s2, o);
        }
        if (lane < 8)
            accL += cw[lane * 4096 + c] * s1 * inv + cw[lane * 4096 + 2048 + c] * s2 * inv;
    }
    __shared__ float wsum[8][8];
    if (lane < 8) wsum[wid][lane] = accL;
    __syncthreads();
    if (tid < 8) {
        float s = cb[tid];
#pragma unroll
        for (int w2 = 0; w2 < 8; w2++) s += wsum[w2][tid];
        dout[512 + b * 8 + tid] = s;
    }
}

// ===========================================================================
extern "C" void kernel_launch(void* const* d_in, const int* in_sizes, int n_in,
                              void* d_out, int out_size)
{
    const float* r5   = (const float*)d_in[0];
    const float* fc0  = (const float*)d_in[1];
    const float* bng  = (const float*)d_in[2];
    const float* bnb  = (const float*)d_in[3];
    const float* bnm  = (const float*)d_in[4];
    const float* bnv  = (const float*)d_in[5];
    const float* mu0  = (const float*)d_in[6];
    const float* c4w  = (const float*)d_in[7];
    const float* c4b  = (const float*)d_in[8];
    const float* dw   = (const float*)d_in[9];
    const float* db   = (const float*)d_in[10];
    const float* cw   = (const float*)d_in[11];
    const float* cb   = (const float*)d_in[12];
    float* out = (float*)d_out;

    static int smem_set = 0;
    if (!smem_set) {
        cudaFuncSetAttribute(mma_gemm_kernel<0>, cudaFuncAttributeMaxDynamicSharedMemorySize, SM_BYTES);
        cudaFuncSetAttribute(mma_gemm_kernel<1>, cudaFuncAttributeMaxDynamicSharedMemorySize, SM_BYTES);
        cudaFuncSetAttribute(mma_gemm_kernel<2>, cudaFuncAttributeMaxDynamicSharedMemorySize, SM_BYTES);
        cudaFuncSetAttribute(down_kernel, cudaFuncAttributeMaxDynamicSharedMemorySize, DOWN_SMEM);
        smem_set = 1;
    }

    bf16 *fcH, *fcL, *c4H, *c4L;
    cudaGetSymbolAddress((void**)&fcH, g_fcH);
    cudaGetSymbolAddress((void**)&fcL, g_fcL);
    cudaGetSymbolAddress((void**)&c4H, g_c4H);
    cudaGetSymbolAddress((void**)&c4L, g_c4L);

    // ---- prep for conv (launch order keeps conv GEMM at slot #4 for ncu) ----
    fc0_perm_kernel<<<2048, 256>>>(fc0);
    r5P_zero_kernel<<<1024, 256>>>();
    r5P_fill_kernel<<<dim3(64, 64, 7), dim3(32, 8)>>>(r5);

    // ---- conv3x3 + BN + ReLU (launch #4 -> profiled) ----
    mma_gemm_kernel<2><<<dim3(49, 4), 256, SM_BYTES>>>(fcH, fcL, r5, nullptr, bng, bnb, bnm, bnv);

    // c4 weight split only needed before conv4 passes
    cvt_split_kernel<<<2048, 256>>>(c4w, c4H, c4L, (size_t)C1 * K4);
    em_kernel<<<64, 256>>>(mu0);
    x1T_kernel<<<dim3(64, 14), 256>>>();

    // ---- conv4 pass 1 & 2 ----
    mma_gemm_kernel<0><<<dim3(49, 16), 256, SM_BYTES>>>(c4H, c4L, r5, c4b, nullptr, nullptr, nullptr, nullptr);
    mma_gemm_kernel<1><<<dim3(49, 16), 256, SM_BYTES>>>(c4H, c4L, r5, c4b, nullptr, nullptr, nullptr, nullptr);
    down_kernel<<<dim3(64, 2), 256, DOWN_SMEM>>>(dw, db);
    pool_kernel<<<64, 256>>>(out);
    out2_kernel<<<64, 256>>>(r5, cw, cb, out);
}

// round 12
// speedup vs baseline: 1.5646x; 1.5065x over previous
#include <cuda_runtime.h>
#include <cuda_fp16.h>
#include <cstdint>

#define BATCH 64
#define NPIX  196
#define C1    2048
#define C2    512
#define KCONV 18432
#define K4    4096
#define EPSF  1e-6f

typedef __half h16;

// ---------------- scratch (device globals; no allocation) ----------------
__device__ float g_x [(size_t)BATCH * C2 * NPIX];   // conv+bn+relu output (fp32)
__device__ float g_x2[(size_t)BATCH * C2 * NPIX];   // GCEM output (fp32)
__device__ float g_zt[(size_t)BATCH * 8  * NPIX];   // attention maps (fp32)
__device__ float g_xb[(size_t)BATCH * C1 * NPIX];   // conv4(concat) output (fp32)
__device__ float g_xd[(size_t)BATCH * 32 * NPIX];   // downconv (fp32)
__device__ float g_xc[(size_t)BATCH * NPIX];        // pooled attention map (fp32)

// fp16 operands: weights single-precision fp16; B-side hi/lo split
__device__ __align__(128) h16 g_fcH [(size_t)C2 * KCONV];   // fc0 permuted: k=(kh*3+kw)*2048+ci
__device__ __align__(128) h16 g_c4H [(size_t)C1 * K4];
__device__ __align__(128) h16 g_r5PH[(size_t)BATCH * 256 * C1];  // padded transpose [b][16][16][c]
__device__ __align__(128) h16 g_r5PL[(size_t)BATCH * 256 * C1];
__device__ __align__(128) h16 g_x1TH[(size_t)BATCH * NPIX * K4]; // [col][kc]
__device__ __align__(128) h16 g_x1TL[(size_t)BATCH * NPIX * K4];
__device__ __align__(128) h16 g_tTH [(size_t)BATCH * NPIX * C1]; // [col][c]
__device__ __align__(128) h16 g_tTL [(size_t)BATCH * NPIX * C1];

// ===========================================================================
// helpers
// ===========================================================================
__device__ __forceinline__ void mma_f16(float* d, const uint32_t* a, const uint32_t* b)
{
    asm volatile(
        "mma.sync.aligned.m16n8k16.row.col.f32.f16.f16.f32 "
        "{%0,%1,%2,%3}, {%4,%5,%6,%7}, {%8,%9}, {%0,%1,%2,%3};"
        : "+f"(d[0]), "+f"(d[1]), "+f"(d[2]), "+f"(d[3])
        : "r"(a[0]), "r"(a[1]), "r"(a[2]), "r"(a[3]), "r"(b[0]), "r"(b[1]));
}
__device__ __forceinline__ uint32_t lds32(const h16* base, int elem)
{
    return *(const uint32_t*)(base + elem);
}
__device__ __forceinline__ void fsplit(float v, h16& h, h16& l)
{
    h = __float2half_rn(v);
    l = __float2half_rn(v - __half2float(h));
}
__device__ __forceinline__ uint32_t smem_u32(const void* p) {
    uint32_t a;
    asm("{ .reg .u64 t; cvta.to.shared.u64 t, %1; cvt.u32.u64 %0, t; }" : "=r"(a) : "l"(p));
    return a;
}
__device__ __forceinline__ void cpa16(uint32_t dst, const void* src) {
    asm volatile("cp.async.cg.shared.global [%0], [%1], 16;" :: "r"(dst), "l"(src));
}
__device__ __forceinline__ void cpa_commit() {
    asm volatile("cp.async.commit_group;" ::: "memory");
}

// ===========================================================================
// prep kernels
// ===========================================================================
// c4w fp32 -> single fp16
__global__ void cvt_h_kernel(const float* __restrict__ src, h16* __restrict__ h, size_t n)
{
    for (size_t i = (size_t)blockIdx.x * blockDim.x + threadIdx.x; i < n;
         i += (size_t)gridDim.x * blockDim.x)
        h[i] = __float2half_rn(src[i]);
}

// fc0 [m][ci*9 + kh*3 + kw] -> g_fcH [m][(kh*3+kw)*2048 + ci] (single fp16)
__global__ void fc0_perm_kernel(const float* __restrict__ src)
{
    for (size_t i = (size_t)blockIdx.x * blockDim.x + threadIdx.x;
         i < (size_t)C2 * KCONV; i += (size_t)gridDim.x * blockDim.x) {
        size_t m = i / KCONV;
        int kk = (int)(i - m * KCONV);
        int s = kk >> 11, ci = kk & 2047;
        g_fcH[i] = __float2half_rn(src[m * KCONV + (size_t)ci * 9 + s]);
    }
}

// zero-fill padded r5P (both hi and lo)
__global__ void r5P_zero_kernel()
{
    size_t n4 = (size_t)BATCH * 256 * C1 / 4;
    uint2 z = make_uint2(0u, 0u);
    uint2* ph = (uint2*)g_r5PH;
    uint2* pl = (uint2*)g_r5PL;
    for (size_t i = (size_t)blockIdx.x * blockDim.x + threadIdx.x; i < n4;
         i += (size_t)gridDim.x * blockDim.x) {
        ph[i] = z; pl[i] = z;
    }
}

// interior fill: r5 [b][c][n] -> r5P [b][h+1][w+1][c] hi/lo (transpose via smem)
__global__ void r5P_fill_kernel(const float* __restrict__ r5)
{
    __shared__ float tile[32][33];
    const int b = blockIdx.x, c0 = blockIdx.y * 32, n0 = blockIdx.z * 32;
    const int tx = threadIdx.x, ty = threadIdx.y;   // 32 x 8
#pragma unroll
    for (int j = 0; j < 4; j++) {
        int c = c0 + ty + j * 8, n = n0 + tx;
        if (n < NPIX) tile[ty + j * 8][tx] = r5[((size_t)b * C1 + c) * NPIX + n];
    }
    __syncthreads();
#pragma unroll
    for (int j = 0; j < 4; j++) {
        int n = n0 + ty + j * 8, c = c0 + tx;
        if (n < NPIX) {
            int h = n / 14, w = n - h * 14;
            h16 hh, ll;
            fsplit(tile[tx][ty + j * 8], hh, ll);
            size_t o = (((size_t)b * 16 + h + 1) * 16 + (w + 1)) * C1 + c;
            g_r5PH[o] = hh; g_r5PL[o] = ll;
        }
    }
}

// ===========================================================================
// Unified tensor-core GEMM: block 128x128, chunk 32, 4-stage cp.async pipeline
// 256 threads / 8 warps in 2(m) x 4(n); warp tile 64x32. fp16 2-term:
//   D = Ah * (Bh + Bl)   (A single fp16, B hi/lo split)
// MODE 0: A=c4w,  B=x1T,             out tT = r5*(acc+bias)  (fp16 split)
// MODE 1: A=c4w,  B=[tT;r5P-center], out g_xb = acc+bias     (fp32)
// MODE 2: A=fc0P, B=shifted r5P,     out g_x = relu(BN(acc)) (fp32)
// ===========================================================================
#define SROW 40
#define MATE (128 * SROW)     // 5120 elems per matrix tile
#define STGE (3 * MATE)       // 15360 elems per stage (Ah, Bh, Bl)
#define STGB (STGE * 2)       // 30720 bytes per stage
#define NSTG 4
#define SM_BYTES (NSTG * STGB)  // 122880

template <int MODE>
__global__ void __launch_bounds__(256, 1) mma_gemm_kernel(
    const h16* __restrict__ Aw,
    const float* __restrict__ r5, const float* __restrict__ bias,
    const float* __restrict__ gamma, const float* __restrict__ beta,
    const float* __restrict__ mean,  const float* __restrict__ var)
{
    constexpr int KTOT = (MODE == 2) ? KCONV : K4;
    constexpr int NC = KTOT / 32;

    extern __shared__ h16 sm[];
    const uint32_t sb = smem_u32(sm);

    const int tid = threadIdx.x;
    const int wid = tid >> 5, lane = tid & 31;
    const int g = lane >> 2, t4 = lane & 3;
    const int warp_m = wid >> 2, warp_n = wid & 3;   // 2 x 4, warp tile 64x32
    const int m0 = blockIdx.y * 128, col0 = blockIdx.x * 128;

    // loader mapping: thread -> (row = tid>>1, 16-elem half = tid&1); 32B granules
    const int rowL = tid >> 1;
    const int half16 = (tid & 1) * 16;
    const h16* gA = Aw + (size_t)(m0 + rowL) * KTOT + half16;

    const int colL = col0 + rowL;
    const int bB = colL / NPIX, pB = colL - bB * NPIX;
    const int hB = pB / 14, wB = pB - hB * 14;

    const h16 *bHsrc0, *bLsrc0;
    if (MODE == 0) {
        bHsrc0 = g_x1TH + (size_t)colL * K4 + half16;
        bLsrc0 = g_x1TL + (size_t)colL * K4 + half16;
    } else {
        bHsrc0 = g_tTH + (size_t)colL * C1 + half16;    // MODE1 k<2048
        bLsrc0 = g_tTL + (size_t)colL * C1 + half16;
    }
    const size_t padBase = (((size_t)bB * 16 + hB) * 16 + wB) * C1 + half16;
    const h16* pPH = g_r5PH + padBase;
    const h16* pPL = g_r5PL + padBase;

    const uint32_t dBase = sb + (uint32_t)(rowL * SROW + half16) * 2;

    auto load_stage = [&](int st, int k0) {
        uint32_t d = dBase + (uint32_t)st * STGB;
        const h16* srcA = gA + k0;
        const h16 *srcBh, *srcBl;
        if (MODE == 0) {
            srcBh = bHsrc0 + k0; srcBl = bLsrc0 + k0;
        } else if (MODE == 1) {
            if (k0 < 2048) { srcBh = bHsrc0 + k0; srcBl = bLsrc0 + k0; }
            else {
                size_t o = (size_t)(1 * 16 + 1) * C1 + (k0 - 2048);  // center shift
                srcBh = pPH + o; srcBl = pPL + o;
            }
        } else {
            int s = k0 >> 11, coff = k0 & 2047;
            int kh = s / 3, kw = s - kh * 3;
            size_t o = (size_t)(kh * 16 + kw) * C1 + coff;
            srcBh = pPH + o; srcBl = pPL + o;
        }
        cpa16(d,                srcA);   cpa16(d + 16,                srcA  + 8);
        cpa16(d + MATE * 2,     srcBh);  cpa16(d + MATE * 2 + 16,     srcBh + 8);
        cpa16(d + MATE * 4,     srcBl);  cpa16(d + MATE * 4 + 16,     srcBl + 8);
        cpa_commit();
    };

    float acc[4][4][4];
#pragma unroll
    for (int i = 0; i < 4; i++)
#pragma unroll
        for (int j = 0; j < 4; j++)
#pragma unroll
            for (int u = 0; u < 4; u++) acc[i][j][u] = 0.f;

    // prologue: 3 stages in flight
    load_stage(0, 0);
    load_stage(1, 32);
    load_stage(2, 64);

    for (int c = 0; c < NC; c++) {
        asm volatile("cp.async.wait_group 2;" ::: "memory");
        __syncthreads();   // publishes stage c; proves compute(c-1) finished
        if (c + 3 < NC) load_stage((c + 3) & (NSTG - 1), (c + 3) * 32);
        else            cpa_commit();   // empty group keeps count uniform

        const h16* pAh = sm + (size_t)(c & (NSTG - 1)) * STGE;
        const h16* pBh = pAh + MATE;
        const h16* pBl = pAh + 2 * MATE;

#pragma unroll
        for (int kk = 0; kk < 32; kk += 16) {
            uint32_t aH[4][4], bH[4][2], bL[4][2];
#pragma unroll
            for (int fm = 0; fm < 4; fm++) {
                int rb = (warp_m * 64 + fm * 16 + g) * SROW + kk + 2 * t4;
                aH[fm][0] = lds32(pAh, rb);
                aH[fm][1] = lds32(pAh, rb + 8 * SROW);
                aH[fm][2] = lds32(pAh, rb + 8);
                aH[fm][3] = lds32(pAh, rb + 8 * SROW + 8);
            }
#pragma unroll
            for (int fn = 0; fn < 4; fn++) {
                int nb = (warp_n * 32 + fn * 8 + g) * SROW + kk + 2 * t4;
                bH[fn][0] = lds32(pBh, nb);
                bH[fn][1] = lds32(pBh, nb + 8);
                bL[fn][0] = lds32(pBl, nb);
                bL[fn][1] = lds32(pBl, nb + 8);
            }
#pragma unroll
            for (int fm = 0; fm < 4; fm++)
#pragma unroll
                for (int fn = 0; fn < 4; fn++) {
                    mma_f16(acc[fm][fn], aH[fm], bH[fn]);
                    mma_f16(acc[fm][fn], aH[fm], bL[fn]);
                }
        }
    }

    // ---- epilogue ----
    float sc[4][2], sh[4][2];
#pragma unroll
    for (int fm = 0; fm < 4; fm++)
#pragma unroll
        for (int hf = 0; hf < 2; hf++) {
            int m = m0 + warp_m * 64 + fm * 16 + g + hf * 8;
            if (MODE == 2) {
                float s = gamma[m] / sqrtf(var[m] + 1e-5f);
                sc[fm][hf] = s;
                sh[fm][hf] = beta[m] - mean[m] * s;
            } else {
                sc[fm][hf] = 1.f;
                sh[fm][hf] = bias[m];
            }
        }
#pragma unroll
    for (int fm = 0; fm < 4; fm++) {
#pragma unroll
        for (int fn = 0; fn < 4; fn++) {
#pragma unroll
            for (int u = 0; u < 4; u++) {
                int hf = u >> 1;
                int m = m0 + warp_m * 64 + fm * 16 + g + hf * 8;
                int col = col0 + warp_n * 32 + fn * 8 + 2 * t4 + (u & 1);
                int bo = col / NPIX, n = col - bo * NPIX;
                float vv = acc[fm][fn][u] * sc[fm][hf] + sh[fm][hf];
                if (MODE == 2) {
                    g_x[((size_t)bo * C2 + m) * NPIX + n] = fmaxf(vv, 0.f);
                } else if (MODE == 1) {
                    g_xb[((size_t)bo * C1 + m) * NPIX + n] = vv;
                } else {
                    float tv = r5[((size_t)bo * C1 + m) * NPIX + n] * vv;
                    h16 hh, ll;
                    fsplit(tv, hh, ll);
                    size_t o = (size_t)col * C1 + m;
                    g_tTH[o] = hh; g_tTL[o] = ll;
                }
            }
        }
    }
}

// ===========================================================================
// EM attention (stage_num=3), one block per batch
// ===========================================================================
__global__ void __launch_bounds__(256) em_kernel(const float* __restrict__ mu0)
{
    const int b = blockIdx.x;
    const int tid = threadIdx.x, lane = tid & 31, wid = tid >> 5;
    const float* xb = g_x + (size_t)b * C2 * NPIX;

    __shared__ float mu[C2 * 8];
    __shared__ float z[NPIX * 8];
    __shared__ float norm[8], colsum[8];

    {
        float s = 0.f;
        for (int c = lane; c < C2; c += 32) { float v = mu0[c * 8 + wid]; s += v * v; }
#pragma unroll
        for (int o = 16; o; o >>= 1) s += __shfl_xor_sync(0xffffffffu, s, o);
        if (!lane) norm[wid] = sqrtf(s) + EPSF;
    }
    __syncthreads();
    for (int i = tid; i < C2 * 8; i += 256) mu[i] = mu0[i] / norm[i & 7];
    __syncthreads();

    for (int it = 0; it < 3; ++it) {
        if (tid < NPIX) {
            float l[8];
#pragma unroll
            for (int k = 0; k < 8; k++) l[k] = 0.f;
            for (int c = 0; c < C2; c++) {
                float xv = xb[c * NPIX + tid];
#pragma unroll
                for (int k = 0; k < 8; k++) l[k] += xv * mu[c * 8 + k];
            }
            float mx = l[0];
#pragma unroll
            for (int k = 1; k < 8; k++) mx = fmaxf(mx, l[k]);
            float e[8], s = 0.f;
#pragma unroll
            for (int k = 0; k < 8; k++) { e[k] = expf(l[k] - mx); s += e[k]; }
            float inv = 1.f / s;
#pragma unroll
            for (int k = 0; k < 8; k++) z[tid * 8 + k] = e[k] * inv;
        }
        __syncthreads();
        {
            float s = 0.f;
            for (int n = lane; n < NPIX; n += 32) s += z[n * 8 + wid];
#pragma unroll
            for (int o = 16; o; o >>= 1) s += __shfl_xor_sync(0xffffffffu, s, o);
            if (!lane) colsum[wid] = s + EPSF;
        }
        __syncthreads();
        for (int o = tid; o < C2 * 8; o += 256) {
            int c = o >> 3, k = o & 7;
            const float* xr = xb + c * NPIX;
            float s = 0.f;
            for (int n = 0; n < NPIX; n++) s += xr[n] * z[n * 8 + k];
            mu[o] = s / colsum[k];
        }
        __syncthreads();
        {
            float s = 0.f;
            for (int c = lane; c < C2; c += 32) { float v = mu[c * 8 + wid]; s += v * v; }
#pragma unroll
            for (int o = 16; o; o >>= 1) s += __shfl_xor_sync(0xffffffffu, s, o);
            if (!lane) norm[wid] = sqrtf(s) + EPSF;
        }
        __syncthreads();
        for (int i = tid; i < C2 * 8; i += 256) mu[i] /= norm[i & 7];
        __syncthreads();
    }
    if (tid < NPIX) {
        float zr[8];
#pragma unroll
        for (int k = 0; k < 8; k++) zr[k] = z[tid * 8 + k];
        float* x2o = g_x2 + (size_t)b * C2 * NPIX;
        for (int c = 0; c < C2; c++) {
            float s = 0.f;
#pragma unroll
            for (int k = 0; k < 8; k++) s += mu[c * 8 + k] * zr[k];
            float v = xb[c * NPIX + tid] + s;
            x2o[c * NPIX + tid] = fmaxf(v, 0.f);
        }
#pragma unroll
        for (int k = 0; k < 8; k++) g_zt[((size_t)b * 8 + k) * NPIX + tid] = zr[k];
    }
}

// ===========================================================================
// x1T: x1T[(b*196+h*14+v)][k*512+c] = sum_w x2[b,c,h*14+w] * zt[b,k,w*14+v]
// ===========================================================================
__global__ void __launch_bounds__(256) x1T_kernel()
{
    const int b = blockIdx.x, h = blockIdx.y;
    const int tid = threadIdx.x, lane = tid & 31, wid = tid >> 5;

    __shared__ float x2s[C2 * 14];
    __shared__ float zts[8 * NPIX];
    for (int i = tid; i < C2 * 14; i += 256) {
        int c = i / 14, w = i - c * 14;
        x2s[i] = g_x2[((size_t)b * C2 + c) * NPIX + h * 14 + w];
    }
    for (int i = tid; i < 8 * NPIX; i += 256) zts[i] = g_zt[(size_t)b * 8 * NPIX + i];
    __syncthreads();

    for (int ci = 0; ci < 2; ci++) {
        const int c = wid * 64 + ci * 32 + lane;
        float xv[14];
#pragma unroll
        for (int w = 0; w < 14; w++) xv[w] = x2s[c * 14 + w];
#pragma unroll
        for (int k = 0; k < 8; k++) {
            float out[14];
#pragma unroll
            for (int v = 0; v < 14; v++) out[v] = 0.f;
#pragma unroll
            for (int w = 0; w < 14; w++) {
                float a = xv[w];
                const float* zp = zts + k * NPIX + w * 14;
#pragma unroll
                for (int v = 0; v < 14; v++) out[v] += a * zp[v];
            }
#pragma unroll
            for (int v = 0; v < 14; v++) {
                h16 hh, ll;
                fsplit(out[v], hh, ll);
                size_t o = ((size_t)b * NPIX + h * 14 + v) * K4 + k * C2 + c;
                g_x1TH[o] = hh; g_x1TL[o] = ll;
            }
        }
    }
}

// ===========================================================================
// downconv 2048->32 (16 output channels per block, dynamic smem weights)
// ===========================================================================
__global__ void __launch_bounds__(256) down_kernel(
    const float* __restrict__ dw, const float* __restrict__ db)
{
    extern __shared__ float ws[];     // 16 * 2048 floats
    const int b = blockIdx.x, jg = blockIdx.y, tid = threadIdx.x;
    for (int i = tid; i < 16 * 2048; i += 256) ws[i] = dw[jg * 16 * 2048 + i];
    __syncthreads();
    if (tid < NPIX) {
        float acc[16];
#pragma unroll
        for (int j = 0; j < 16; j++) acc[j] = db[jg * 16 + j];
        const float* xp = g_xb + (size_t)b * C1 * NPIX + tid;
        for (int c = 0; c < 2048; c++) {
            float v = xp[(size_t)c * NPIX];
#pragma unroll
            for (int j = 0; j < 16; j++) acc[j] += ws[j * 2048 + c] * v;
        }
#pragma unroll
        for (int j = 0; j < 16; j++)
            g_xd[((size_t)b * 32 + jg * 16 + j) * NPIX + tid] = acc[j];
    }
}
#define DOWN_SMEM (16 * 2048 * 4)

// ===========================================================================
// GAP + class-wise pools -> xg (output[0:512]) and xc map
// ===========================================================================
__global__ void __launch_bounds__(256) pool_kernel(float* __restrict__ dout)
{
    const int b = blockIdx.x, tid = threadIdx.x;
    __shared__ float gap[32];
    __shared__ float xgs[8];
    if (tid < 32) {
        const float* p = g_xd + ((size_t)b * 32 + tid) * NPIX;
        float s = 0.f;
        for (int n = 0; n < NPIX; n++) s += p[n];
        gap[tid] = s * (1.f / NPIX);
    }
    __syncthreads();
    if (tid < 8) {
        float g = 0.25f * (gap[4 * tid] + gap[4 * tid + 1] + gap[4 * tid + 2] + gap[4 * tid + 3]);
        xgs[tid] = g;
        dout[b * 8 + tid] = g;
    }
    __syncthreads();
    if (tid < NPIX) {
        const float* p = g_xd + (size_t)b * 32 * NPIX + tid;
        float s = 0.f;
#pragma unroll
        for (int pp = 0; pp < 8; pp++) {
            float cp = 0.25f * (p[(4 * pp + 0) * NPIX] + p[(4 * pp + 1) * NPIX] +
                                p[(4 * pp + 2) * NPIX] + p[(4 * pp + 3) * NPIX]);
            s += cp * xgs[pp];
        }
        g_xc[b * NPIX + tid] = s * 0.125f;
    }
}

// ===========================================================================
// cls head -> out2 (output[512:1024])
// ===========================================================================
__global__ void __launch_bounds__(256) out2_kernel(
    const float* __restrict__ r5, const float* __restrict__ cw,
    const float* __restrict__ cb, float* __restrict__ dout)
{
    const int b = blockIdx.x, tid = threadIdx.x, lane = tid & 31, wid = tid >> 5;
    __shared__ float xcs[NPIX];
    for (int i = tid; i < NPIX; i += 256) xcs[i] = g_xc[b * NPIX + i];
    __syncthreads();
    const float inv = 1.f / NPIX;
    float accL = 0.f;
    for (int c = wid; c < 2048; c += 8) {
        const float* rp = r5 + ((size_t)b * C1 + c) * NPIX;
        float s1 = 0.f, s2 = 0.f;
        for (int n = lane; n < NPIX; n += 32) { float v = rp[n]; s1 += v; s2 += v * xcs[n]; }
#pragma unroll
        for (int o = 16; o; o >>= 1) {
            s1 += __shfl_xor_sync(0xffffffffu, s1, o);
            s2 += __shfl_xor_sync(0xffffffffu, s2, o);
        }
        if (lane < 8)
            accL += cw[lane * 4096 + c] * s1 * inv + cw[lane * 4096 + 2048 + c] * s2 * inv;
    }
    __shared__ float wsum[8][8];
    if (lane < 8) wsum[wid][lane] = accL;
    __syncthreads();
    if (tid < 8) {
        float s = cb[tid];
#pragma unroll
        for (int w2 = 0; w2 < 8; w2++) s += wsum[w2][tid];
        dout[512 + b * 8 + tid] = s;
    }
}

// ===========================================================================
extern "C" void kernel_launch(void* const* d_in, const int* in_sizes, int n_in,
                              void* d_out, int out_size)
{
    const float* r5   = (const float*)d_in[0];
    const float* fc0  = (const float*)d_in[1];
    const float* bng  = (const float*)d_in[2];
    const float* bnb  = (const float*)d_in[3];
    const float* bnm  = (const float*)d_in[4];
    const float* bnv  = (const float*)d_in[5];
    const float* mu0  = (const float*)d_in[6];
    const float* c4w  = (const float*)d_in[7];
    const float* c4b  = (const float*)d_in[8];
    const float* dw   = (const float*)d_in[9];
    const float* db   = (const float*)d_in[10];
    const float* cw   = (const float*)d_in[11];
    const float* cb   = (const float*)d_in[12];
    float* out = (float*)d_out;

    static int smem_set = 0;
    if (!smem_set) {
        cudaFuncSetAttribute(mma_gemm_kernel<0>, cudaFuncAttributeMaxDynamicSharedMemorySize, SM_BYTES);
        cudaFuncSetAttribute(mma_gemm_kernel<1>, cudaFuncAttributeMaxDynamicSharedMemorySize, SM_BYTES);
        cudaFuncSetAttribute(mma_gemm_kernel<2>, cudaFuncAttributeMaxDynamicSharedMemorySize, SM_BYTES);
        cudaFuncSetAttribute(down_kernel, cudaFuncAttributeMaxDynamicSharedMemorySize, DOWN_SMEM);
        smem_set = 1;
    }

    h16 *fcH, *c4H;
    cudaGetSymbolAddress((void**)&fcH, g_fcH);
    cudaGetSymbolAddress((void**)&c4H, g_c4H);

    // ---- prep for conv (launch order keeps conv GEMM at slot #4 for ncu) ----
    fc0_perm_kernel<<<2048, 256>>>(fc0);
    r5P_zero_kernel<<<1024, 256>>>();
    r5P_fill_kernel<<<dim3(64, 64, 7), dim3(32, 8)>>>(r5);

    // ---- conv3x3 + BN + ReLU (launch #4 -> profiled) ----
    mma_gemm_kernel<2><<<dim3(98, 4), 256, SM_BYTES>>>(fcH, r5, nullptr, bng, bnb, bnm, bnv);

    // c4 weight convert only needed before conv4 passes
    cvt_h_kernel<<<2048, 256>>>(c4w, c4H, (size_t)C1 * K4);
    em_kernel<<<64, 256>>>(mu0);
    x1T_kernel<<<dim3(64, 14), 256>>>();

    // ---- conv4 pass 1 & 2 ----
    mma_gemm_kernel<0><<<dim3(98, 16), 256, SM_BYTES>>>(c4H, r5, c4b, nullptr, nullptr, nullptr, nullptr);
    mma_gemm_kernel<1><<<dim3(98, 16), 256, SM_BYTES>>>(c4H, r5, c4b, nullptr, nullptr, nullptr, nullptr);
    down_kernel<<<dim3(64, 2), 256, DOWN_SMEM>>>(dw, db);
    pool_kernel<<<64, 256>>>(out);
    out2_kernel<<<64, 256>>>(r5, cw, cb, out);
}

// round 13
// speedup vs baseline: 2.3033x; 1.4721x over previous
#include <cuda_runtime.h>
#include <cuda_fp16.h>
#include <cstdint>

#define BATCH 64
#define NPIX  196
#define C1    2048
#define C2    512
#define KCONV 18432
#define K4    4096
#define EPSF  1e-6f

typedef __half h16;

// ---------------- scratch (device globals; no allocation) ----------------
__device__ float g_x [(size_t)BATCH * C2 * NPIX];   // conv+bn+relu output (fp32)
__device__ float g_x2[(size_t)BATCH * C2 * NPIX];   // GCEM output (fp32)
__device__ float g_zt[(size_t)BATCH * 8  * NPIX];   // attention maps (fp32)
__device__ float g_xb[(size_t)BATCH * C1 * NPIX];   // conv4(concat) output (fp32)
__device__ float g_xd[(size_t)BATCH * 32 * NPIX];   // downconv (fp32)
__device__ float g_xc[(size_t)BATCH * NPIX];        // pooled attention map (fp32)

// fp16 operands (all single-precision fp16; 1-term MMA)
__device__ __align__(128) h16 g_fcH [(size_t)C2 * KCONV];   // fc0 permuted: k=(kh*3+kw)*2048+ci
__device__ __align__(128) h16 g_c4H [(size_t)C1 * K4];
__device__ __align__(128) h16 g_r5PH[(size_t)BATCH * 256 * C1];  // padded transpose [b][16][16][c]
__device__ __align__(128) h16 g_x1TH[(size_t)BATCH * NPIX * K4]; // [col][kc]
__device__ __align__(128) h16 g_tTH [(size_t)BATCH * NPIX * C1]; // [col][c]

// ===========================================================================
// helpers
// ===========================================================================
__device__ __forceinline__ void mma_f16(float* d, const uint32_t* a, const uint32_t* b)
{
    asm volatile(
        "mma.sync.aligned.m16n8k16.row.col.f32.f16.f16.f32 "
        "{%0,%1,%2,%3}, {%4,%5,%6,%7}, {%8,%9}, {%0,%1,%2,%3};"
        : "+f"(d[0]), "+f"(d[1]), "+f"(d[2]), "+f"(d[3])
        : "r"(a[0]), "r"(a[1]), "r"(a[2]), "r"(a[3]), "r"(b[0]), "r"(b[1]));
}
__device__ __forceinline__ uint32_t lds32(const h16* base, int elem)
{
    return *(const uint32_t*)(base + elem);
}
__device__ __forceinline__ uint32_t smem_u32(const void* p) {
    uint32_t a;
    asm("{ .reg .u64 t; cvta.to.shared.u64 t, %1; cvt.u32.u64 %0, t; }" : "=r"(a) : "l"(p));
    return a;
}
__device__ __forceinline__ void cpa16(uint32_t dst, const void* src) {
    asm volatile("cp.async.cg.shared.global [%0], [%1], 16;" :: "r"(dst), "l"(src));
}
__device__ __forceinline__ void cpa_commit() {
    asm volatile("cp.async.commit_group;" ::: "memory");
}

// ===========================================================================
// prep kernels
// ===========================================================================
// fp32 -> fp16
__global__ void cvt_h_kernel(const float* __restrict__ src, h16* __restrict__ h, size_t n)
{
    for (size_t i = (size_t)blockIdx.x * blockDim.x + threadIdx.x; i < n;
         i += (size_t)gridDim.x * blockDim.x)
        h[i] = __float2half_rn(src[i]);
}

// fc0 [m][ci*9 + kh*3 + kw] -> g_fcH [m][(kh*3+kw)*2048 + ci] (fp16)
__global__ void fc0_perm_kernel(const float* __restrict__ src)
{
    for (size_t i = (size_t)blockIdx.x * blockDim.x + threadIdx.x;
         i < (size_t)C2 * KCONV; i += (size_t)gridDim.x * blockDim.x) {
        size_t m = i / KCONV;
        int kk = (int)(i - m * KCONV);
        int s = kk >> 11, ci = kk & 2047;
        g_fcH[i] = __float2half_rn(src[m * KCONV + (size_t)ci * 9 + s]);
    }
}

// zero-fill padded r5P
__global__ void r5P_zero_kernel()
{
    size_t n4 = (size_t)BATCH * 256 * C1 / 4;
    uint2 z = make_uint2(0u, 0u);
    uint2* ph = (uint2*)g_r5PH;
    for (size_t i = (size_t)blockIdx.x * blockDim.x + threadIdx.x; i < n4;
         i += (size_t)gridDim.x * blockDim.x)
        ph[i] = z;
}

// interior fill: r5 [b][c][n] -> r5P [b][h+1][w+1][c] (transpose via smem)
__global__ void r5P_fill_kernel(const float* __restrict__ r5)
{
    __shared__ float tile[32][33];
    const int b = blockIdx.x, c0 = blockIdx.y * 32, n0 = blockIdx.z * 32;
    const int tx = threadIdx.x, ty = threadIdx.y;   // 32 x 8
#pragma unroll
    for (int j = 0; j < 4; j++) {
        int c = c0 + ty + j * 8, n = n0 + tx;
        if (n < NPIX) tile[ty + j * 8][tx] = r5[((size_t)b * C1 + c) * NPIX + n];
    }
    __syncthreads();
#pragma unroll
    for (int j = 0; j < 4; j++) {
        int n = n0 + ty + j * 8, c = c0 + tx;
        if (n < NPIX) {
            int h = n / 14, w = n - h * 14;
            size_t o = (((size_t)b * 16 + h + 1) * 16 + (w + 1)) * C1 + c;
            g_r5PH[o] = __float2half_rn(tile[tx][ty + j * 8]);
        }
    }
}

// ===========================================================================
// Unified tensor-core GEMM: block 128x128, chunk 32, 4-stage cp.async pipeline
// 256 threads / 8 warps in 2(m) x 4(n); warp tile 64x32. 1-term fp16:
//   D = A * B   (both single fp16, fp32 accum)
// MODE 0: A=c4w,  B=x1T,             out tT = r5*(acc+bias)  (fp16)
// MODE 1: A=c4w,  B=[tT;r5P-center], out g_xb = acc+bias     (fp32)
// MODE 2: A=fc0P, B=shifted r5P,     out g_x = relu(BN(acc)) (fp32)
// ===========================================================================
#define SROW 40
#define MATE (128 * SROW)     // 5120 elems per matrix tile
#define STGE (2 * MATE)       // 10240 elems per stage (A, B)
#define STGB (STGE * 2)       // 20480 bytes per stage
#define NSTG 4
#define SM_BYTES (NSTG * STGB)  // 81920

template <int MODE>
__global__ void __launch_bounds__(256, 2) mma_gemm_kernel(
    const h16* __restrict__ Aw,
    const float* __restrict__ r5, const float* __restrict__ bias,
    const float* __restrict__ gamma, const float* __restrict__ beta,
    const float* __restrict__ mean,  const float* __restrict__ var)
{
    constexpr int KTOT = (MODE == 2) ? KCONV : K4;
    constexpr int NC = KTOT / 32;

    extern __shared__ h16 sm[];
    const uint32_t sb = smem_u32(sm);

    const int tid = threadIdx.x;
    const int wid = tid >> 5, lane = tid & 31;
    const int g = lane >> 2, t4 = lane & 3;
    const int warp_m = wid >> 2, warp_n = wid & 3;   // 2 x 4, warp tile 64x32
    const int m0 = blockIdx.y * 128, col0 = blockIdx.x * 128;

    // loader mapping: thread -> (row = tid>>1, 16-elem half = tid&1); 32B granules
    const int rowL = tid >> 1;
    const int half16 = (tid & 1) * 16;
    const h16* gA = Aw + (size_t)(m0 + rowL) * KTOT + half16;

    const int colL = col0 + rowL;
    const int bB = colL / NPIX, pB = colL - bB * NPIX;
    const int hB = pB / 14, wB = pB - hB * 14;

    const h16* bHsrc0;
    if (MODE == 0) bHsrc0 = g_x1TH + (size_t)colL * K4 + half16;
    else           bHsrc0 = g_tTH + (size_t)colL * C1 + half16;   // MODE1 k<2048
    const size_t padBase = (((size_t)bB * 16 + hB) * 16 + wB) * C1 + half16;
    const h16* pPH = g_r5PH + padBase;

    const uint32_t dBase = sb + (uint32_t)(rowL * SROW + half16) * 2;

    auto load_stage = [&](int st, int k0) {
        uint32_t d = dBase + (uint32_t)st * STGB;
        const h16* srcA = gA + k0;
        const h16* srcB;
        if (MODE == 0) {
            srcB = bHsrc0 + k0;
        } else if (MODE == 1) {
            if (k0 < 2048) srcB = bHsrc0 + k0;
            else           srcB = pPH + (size_t)(1 * 16 + 1) * C1 + (k0 - 2048);
        } else {
            int s = k0 >> 11, coff = k0 & 2047;
            int kh = s / 3, kw = s - kh * 3;
            srcB = pPH + (size_t)(kh * 16 + kw) * C1 + coff;
        }
        cpa16(d,            srcA);  cpa16(d + 16,            srcA + 8);
        cpa16(d + MATE * 2, srcB);  cpa16(d + MATE * 2 + 16, srcB + 8);
        cpa_commit();
    };

    float acc[4][4][4];
#pragma unroll
    for (int i = 0; i < 4; i++)
#pragma unroll
        for (int j = 0; j < 4; j++)
#pragma unroll
            for (int u = 0; u < 4; u++) acc[i][j][u] = 0.f;

    // prologue: 3 stages in flight
    load_stage(0, 0);
    load_stage(1, 32);
    load_stage(2, 64);

    for (int c = 0; c < NC; c++) {
        asm volatile("cp.async.wait_group 2;" ::: "memory");
        __syncthreads();   // publishes stage c; proves compute(c-1) finished
        if (c + 3 < NC) load_stage((c + 3) & (NSTG - 1), (c + 3) * 32);
        else            cpa_commit();   // empty group keeps count uniform

        const h16* pAh = sm + (size_t)(c & (NSTG - 1)) * STGE;
        const h16* pBh = pAh + MATE;

#pragma unroll
        for (int kk = 0; kk < 32; kk += 16) {
            uint32_t aH[4][4], bH[4][2];
#pragma unroll
            for (int fm = 0; fm < 4; fm++) {
                int rb = (warp_m * 64 + fm * 16 + g) * SROW + kk + 2 * t4;
                aH[fm][0] = lds32(pAh, rb);
                aH[fm][1] = lds32(pAh, rb + 8 * SROW);
                aH[fm][2] = lds32(pAh, rb + 8);
                aH[fm][3] = lds32(pAh, rb + 8 * SROW + 8);
            }
#pragma unroll
            for (int fn = 0; fn < 4; fn++) {
                int nb = (warp_n * 32 + fn * 8 + g) * SROW + kk + 2 * t4;
                bH[fn][0] = lds32(pBh, nb);
                bH[fn][1] = lds32(pBh, nb + 8);
            }
#pragma unroll
            for (int fm = 0; fm < 4; fm++)
#pragma unroll
                for (int fn = 0; fn < 4; fn++)
                    mma_f16(acc[fm][fn], aH[fm], bH[fn]);
        }
    }

    // ---- epilogue ----
    float sc[4][2], sh[4][2];
#pragma unroll
    for (int fm = 0; fm < 4; fm++)
#pragma unroll
        for (int hf = 0; hf < 2; hf++) {
            int m = m0 + warp_m * 64 + fm * 16 + g + hf * 8;
            if (MODE == 2) {
                float s = gamma[m] / sqrtf(var[m] + 1e-5f);
                sc[fm][hf] = s;
                sh[fm][hf] = beta[m] - mean[m] * s;
            } else {
                sc[fm][hf] = 1.f;
                sh[fm][hf] = bias[m];
            }
        }
#pragma unroll
    for (int fm = 0; fm < 4; fm++) {
#pragma unroll
        for (int fn = 0; fn < 4; fn++) {
#pragma unroll
            for (int u = 0; u < 4; u++) {
                int hf = u >> 1;
                int m = m0 + warp_m * 64 + fm * 16 + g + hf * 8;
                int col = col0 + warp_n * 32 + fn * 8 + 2 * t4 + (u & 1);
                int bo = col / NPIX, n = col - bo * NPIX;
                float vv = acc[fm][fn][u] * sc[fm][hf] + sh[fm][hf];
                if (MODE == 2) {
                    g_x[((size_t)bo * C2 + m) * NPIX + n] = fmaxf(vv, 0.f);
                } else if (MODE == 1) {
                    g_xb[((size_t)bo * C1 + m) * NPIX + n] = vv;
                } else {
                    float tv = r5[((size_t)bo * C1 + m) * NPIX + n] * vv;
                    g_tTH[(size_t)col * C1 + m] = __float2half_rn(tv);
                }
            }
        }
    }
}

// ===========================================================================
// EM attention (stage_num=3), one block per batch
// ===========================================================================
__global__ void __launch_bounds__(256) em_kernel(const float* __restrict__ mu0)
{
    const int b = blockIdx.x;
    const int tid = threadIdx.x, lane = tid & 31, wid = tid >> 5;
    const float* xb = g_x + (size_t)b * C2 * NPIX;

    __shared__ float mu[C2 * 8];
    __shared__ float z[NPIX * 8];
    __shared__ float norm[8], colsum[8];

    {
        float s = 0.f;
        for (int c = lane; c < C2; c += 32) { float v = mu0[c * 8 + wid]; s += v * v; }
#pragma unroll
        for (int o = 16; o; o >>= 1) s += __shfl_xor_sync(0xffffffffu, s, o);
        if (!lane) norm[wid] = sqrtf(s) + EPSF;
    }
    __syncthreads();
    for (int i = tid; i < C2 * 8; i += 256) mu[i] = mu0[i] / norm[i & 7];
    __syncthreads();

    for (int it = 0; it < 3; ++it) {
        if (tid < NPIX) {
            float l[8];
#pragma unroll
            for (int k = 0; k < 8; k++) l[k] = 0.f;
            for (int c = 0; c < C2; c++) {
                float xv = xb[c * NPIX + tid];
#pragma unroll
                for (int k = 0; k < 8; k++) l[k] += xv * mu[c * 8 + k];
            }
            float mx = l[0];
#pragma unroll
            for (int k = 1; k < 8; k++) mx = fmaxf(mx, l[k]);
            float e[8], s = 0.f;
#pragma unroll
            for (int k = 0; k < 8; k++) { e[k] = expf(l[k] - mx); s += e[k]; }
            float inv = 1.f / s;
#pragma unroll
            for (int k = 0; k < 8; k++) z[tid * 8 + k] = e[k] * inv;
        }
        __syncthreads();
        {
            float s = 0.f;
            for (int n = lane; n < NPIX; n += 32) s += z[n * 8 + wid];
#pragma unroll
            for (int o = 16; o; o >>= 1) s += __shfl_xor_sync(0xffffffffu, s, o);
            if (!lane) colsum[wid] = s + EPSF;
        }
        __syncthreads();
        for (int o = tid; o < C2 * 8; o += 256) {
            int c = o >> 3, k = o & 7;
            const float* xr = xb + c * NPIX;
            float s = 0.f;
            for (int n = 0; n < NPIX; n++) s += xr[n] * z[n * 8 + k];
            mu[o] = s / colsum[k];
        }
        __syncthreads();
        {
            float s = 0.f;
            for (int c = lane; c < C2; c += 32) { float v = mu[c * 8 + wid]; s += v * v; }
#pragma unroll
            for (int o = 16; o; o >>= 1) s += __shfl_xor_sync(0xffffffffu, s, o);
            if (!lane) norm[wid] = sqrtf(s) + EPSF;
        }
        __syncthreads();
        for (int i = tid; i < C2 * 8; i += 256) mu[i] /= norm[i & 7];
        __syncthreads();
    }
    if (tid < NPIX) {
        float zr[8];
#pragma unroll
        for (int k = 0; k < 8; k++) zr[k] = z[tid * 8 + k];
        float* x2o = g_x2 + (size_t)b * C2 * NPIX;
        for (int c = 0; c < C2; c++) {
            float s = 0.f;
#pragma unroll
            for (int k = 0; k < 8; k++) s += mu[c * 8 + k] * zr[k];
            float v = xb[c * NPIX + tid] + s;
            x2o[c * NPIX + tid] = fmaxf(v, 0.f);
        }
#pragma unroll
        for (int k = 0; k < 8; k++) g_zt[((size_t)b * 8 + k) * NPIX + tid] = zr[k];
    }
}

// ===========================================================================
// x1T: x1T[(b*196+h*14+v)][k*512+c] = sum_w x2[b,c,h*14+w] * zt[b,k,w*14+v]
// ===========================================================================
__global__ void __launch_bounds__(256) x1T_kernel()
{
    const int b = blockIdx.x, h = blockIdx.y;
    const int tid = threadIdx.x, lane = tid & 31, wid = tid >> 5;

    __shared__ float x2s[C2 * 14];
    __shared__ float zts[8 * NPIX];
    for (int i = tid; i < C2 * 14; i += 256) {
        int c = i / 14, w = i - c * 14;
        x2s[i] = g_x2[((size_t)b * C2 + c) * NPIX + h * 14 + w];
    }
    for (int i = tid; i < 8 * NPIX; i += 256) zts[i] = g_zt[(size_t)b * 8 * NPIX + i];
    __syncthreads();

    for (int ci = 0; ci < 2; ci++) {
        const int c = wid * 64 + ci * 32 + lane;
        float xv[14];
#pragma unroll
        for (int w = 0; w < 14; w++) xv[w] = x2s[c * 14 + w];
#pragma unroll
        for (int k = 0; k < 8; k++) {
            float out[14];
#pragma unroll
            for (int v = 0; v < 14; v++) out[v] = 0.f;
#pragma unroll
            for (int w = 0; w < 14; w++) {
                float a = xv[w];
                const float* zp = zts + k * NPIX + w * 14;
#pragma unroll
                for (int v = 0; v < 14; v++) out[v] += a * zp[v];
            }
#pragma unroll
            for (int v = 0; v < 14; v++) {
                size_t o = ((size_t)b * NPIX + h * 14 + v) * K4 + k * C2 + c;
                g_x1TH[o] = __float2half_rn(out[v]);
            }
        }
    }
}

// ===========================================================================
// downconv 2048->32 (16 output channels per block, dynamic smem weights)
// ===========================================================================
__global__ void __launch_bounds__(256) down_kernel(
    const float* __restrict__ dw, const float* __restrict__ db)
{
    extern __shared__ float ws[];     // 16 * 2048 floats
    const int b = blockIdx.x, jg = blockIdx.y, tid = threadIdx.x;
    for (int i = tid; i < 16 * 2048; i += 256) ws[i] = dw[jg * 16 * 2048 + i];
    __syncthreads();
    if (tid < NPIX) {
        float acc[16];
#pragma unroll
        for (int j = 0; j < 16; j++) acc[j] = db[jg * 16 + j];
        const float* xp = g_xb + (size_t)b * C1 * NPIX + tid;
        for (int c = 0; c < 2048; c++) {
            float v = xp[(size_t)c * NPIX];
#pragma unroll
            for (int j = 0; j < 16; j++) acc[j] += ws[j * 2048 + c] * v;
        }
#pragma unroll
        for (int j = 0; j < 16; j++)
            g_xd[((size_t)b * 32 + jg * 16 + j) * NPIX + tid] = acc[j];
    }
}
#define DOWN_SMEM (16 * 2048 * 4)

// ===========================================================================
// GAP + class-wise pools -> xg (output[0:512]) and xc map
// ===========================================================================
__global__ void __launch_bounds__(256) pool_kernel(float* __restrict__ dout)
{
    const int b = blockIdx.x, tid = threadIdx.x;
    __shared__ float gap[32];
    __shared__ float xgs[8];
    if (tid < 32) {
        const float* p = g_xd + ((size_t)b * 32 + tid) * NPIX;
        float s = 0.f;
        for (int n = 0; n < NPIX; n++) s += p[n];
        gap[tid] = s * (1.f / NPIX);
    }
    __syncthreads();
    if (tid < 8) {
        float g = 0.25f * (gap[4 * tid] + gap[4 * tid + 1] + gap[4 * tid + 2] + gap[4 * tid + 3]);
        xgs[tid] = g;
        dout[b * 8 + tid] = g;
    }
    __syncthreads();
    if (tid < NPIX) {
        const float* p = g_xd + (size_t)b * 32 * NPIX + tid;
        float s = 0.f;
#pragma unroll
        for (int pp = 0; pp < 8; pp++) {
            float cp = 0.25f * (p[(4 * pp + 0) * NPIX] + p[(4 * pp + 1) * NPIX] +
                                p[(4 * pp + 2) * NPIX] + p[(4 * pp + 3) * NPIX]);
            s += cp * xgs[pp];
        }
        g_xc[b * NPIX + tid] = s * 0.125f;
    }
}

// ===========================================================================
// cls head -> out2 (output[512:1024])
// ===========================================================================
__global__ void __launch_bounds__(256) out2_kernel(
    const float* __restrict__ r5, const float* __restrict__ cw,
    const float* __restrict__ cb, float* __restrict__ dout)
{
    const int b = blockIdx.x, tid = threadIdx.x, lane = tid & 31, wid = tid >> 5;
    __shared__ float xcs[NPIX];
    for (int i = tid; i < NPIX; i += 256) xcs[i] = g_xc[b * NPIX + i];
    __syncthreads();
    const float inv = 1.f / NPIX;
    float accL = 0.f;
    for (int c = wid; c < 2048; c += 8) {
        const float* rp = r5 + ((size_t)b * C1 + c) * NPIX;
        float s1 = 0.f, s2 = 0.f;
        for (int n = lane; n < NPIX; n += 32) { float v = rp[n]; s1 += v; s2 += v * xcs[n]; }
#pragma unroll
        for (int o = 16; o; o >>= 1) {
            s1 += __shfl_xor_sync(0xffffffffu, s1, o);
            s2 += __shfl_xor_sync(0xffffffffu, s2, o);
        }
        if (lane < 8)
            accL += cw[lane * 4096 + c] * s1 * inv + cw[lane * 4096 + 2048 + c] * s2 * inv;
    }
    __shared__ float wsum[8][8];
    if (lane < 8) wsum[wid][lane] = accL;
    __syncthreads();
    if (tid < 8) {
        float s = cb[tid];
#pragma unroll
        for (int w2 = 0; w2 < 8; w2++) s += wsum[w2][tid];
        dout[512 + b * 8 + tid] = s;
    }
}

// ===========================================================================
extern "C" void kernel_launch(void* const* d_in, const int* in_sizes, int n_in,
                              void* d_out, int out_size)
{
    const float* r5   = (const float*)d_in[0];
    const float* fc0  = (const float*)d_in[1];
    const float* bng  = (const float*)d_in[2];
    const float* bnb  = (const float*)d_in[3];
    const float* bnm  = (const float*)d_in[4];
    const float* bnv  = (const float*)d_in[5];
    const float* mu0  = (const float*)d_in[6];
    const float* c4w  = (const float*)d_in[7];
    const float* c4b  = (const float*)d_in[8];
    const float* dw   = (const float*)d_in[9];
    const float* db   = (const float*)d_in[10];
    const float* cw   = (const float*)d_in[11];
    const float* cb   = (const float*)d_in[12];
    float* out = (float*)d_out;

    static int smem_set = 0;
    if (!smem_set) {
        cudaFuncSetAttribute(mma_gemm_kernel<0>, cudaFuncAttributeMaxDynamicSharedMemorySize, SM_BYTES);
        cudaFuncSetAttribute(mma_gemm_kernel<1>, cudaFuncAttributeMaxDynamicSharedMemorySize, SM_BYTES);
        cudaFuncSetAttribute(mma_gemm_kernel<2>, cudaFuncAttributeMaxDynamicSharedMemorySize, SM_BYTES);
        cudaFuncSetAttribute(down_kernel, cudaFuncAttributeMaxDynamicSharedMemorySize, DOWN_SMEM);
        smem_set = 1;
    }

    h16 *fcH, *c4H;
    cudaGetSymbolAddress((void**)&fcH, g_fcH);
    cudaGetSymbolAddress((void**)&c4H, g_c4H);

    // ---- prep for conv (launch order keeps conv GEMM at slot #4 for ncu) ----
    fc0_perm_kernel<<<2048, 256>>>(fc0);
    r5P_zero_kernel<<<1024, 256>>>();
    r5P_fill_kernel<<<dim3(64, 64, 7), dim3(32, 8)>>>(r5);

    // ---- conv3x3 + BN + ReLU (launch #4 -> profiled) ----
    mma_gemm_kernel<2><<<dim3(98, 4), 256, SM_BYTES>>>(fcH, r5, nullptr, bng, bnb, bnm, bnv);

    // c4 weight convert only needed before conv4 passes
    cvt_h_kernel<<<2048, 256>>>(c4w, c4H, (size_t)C1 * K4);
    em_kernel<<<64, 256>>>(mu0);
    x1T_kernel<<<dim3(64, 14), 256>>>();

    // ---- conv4 pass 1 & 2 ----
    mma_gemm_kernel<0><<<dim3(98, 16), 256, SM_BYTES>>>(c4H, r5, c4b, nullptr, nullptr, nullptr, nullptr);
    mma_gemm_kernel<1><<<dim3(98, 16), 256, SM_BYTES>>>(c4H, r5, c4b, nullptr, nullptr, nullptr, nullptr);
    down_kernel<<<dim3(64, 2), 256, DOWN_SMEM>>>(dw, db);
    pool_kernel<<<64, 256>>>(out);
    out2_kernel<<<64, 256>>>(r5, cw, cb, out);
}